// round 11
// baseline (speedup 1.0000x reference)
#include <cuda_runtime.h>

// ---------------- problem constants ----------------------------------------
#define NMAX 100000
#define EMAX 1600000
#define NGRP 64
#define NODEB 148         // hetero K1: node-GEMM blocks
#define GEMVB 148         // hetero K1: edge-GEMV blocks
#define NB3  148          // fused-tail persistent grid
#define NT3  512
#define GS3  (NB3 * NT3)

// ---------------- scratch (__device__ globals) -----------------------------
__device__ float2   g_kqvv[NMAX * 16];   // per node 32 f: k0..4 @0, (q_s,v_s) @8+2s
__device__ float4   g_aggv[NMAX * 2];    // per node 8 f: conv1 agg in [0..5)
__device__ float4   g_e1a[EMAX];         // per-edge conv1 proj h0..h3 (+bias)
__device__ float    g_e1b[EMAX];         // per-edge conv1 proj h4 (+bias)
__device__ float    g_e2[EMAX];          // per-edge conv2 edge projection (+bias)
__device__ float4   g_kqv2[NMAX];        // conv2 node proj (k2,q2,v2,_)
__device__ float    g_gsum[NGRP * 5];
__device__ float    g_gsq[NGRP * 5];
__device__ float    g_gcnt[NGRP];
__device__ unsigned g_bar;               // grid barrier counter (reset by K1)

// sigmoid via MUFU.TANH: 1 MUFU instead of 2. rel_err ~1e-6, well under 1e-3.
__device__ __forceinline__ float fast_sigmoid(float z) {
    float t;
    asm("tanh.approx.f32 %0, %1;" : "=f"(t) : "f"(z * 0.5f));
    return fmaf(t, 0.5f, 0.5f);
}

// ---- packed f32x2 helpers (ptxas won't emit FFMA2/FADD2 from C++) ---------
__device__ __forceinline__ unsigned long long pack2(float a, float b) {
    unsigned long long r;
    asm("mov.b64 %0, {%1, %2};" : "=l"(r) : "f"(a), "f"(b));
    return r;
}
__device__ __forceinline__ void unpack2(unsigned long long v, float& a, float& b) {
    asm("mov.b64 {%0, %1}, %2;" : "=f"(a), "=f"(b) : "l"(v));
}
__device__ __forceinline__ void fma2(unsigned long long& d,
                                     unsigned long long a, unsigned long long b) {
    asm("fma.rn.f32x2 %0, %1, %2, %0;" : "+l"(d) : "l"(a), "l"(b));
}
__device__ __forceinline__ unsigned long long add2(unsigned long long a,
                                                   unsigned long long b) {
    unsigned long long r;
    asm("add.rn.f32x2 %0, %1, %2;" : "=l"(r) : "l"(a), "l"(b));
    return r;
}

// ---------------------------------------------------------------------------
// K1 (heterogeneous): blocks [0,148) = conv1 node GEMM; blocks [148,296) =
// conv1/conv2 edge-attr GEMV with cross-iteration prefetch. Co-resident
// (2 blocks/SM). Node reduce does a 1-level packed butterfly BEFORE the smem
// transpose, halving smem crossbar traffic (the measured node-side roof).
__global__ __launch_bounds__(256, 2) void k1_hetero(
    const float* __restrict__ x,
    const float* __restrict__ Wk, const float* __restrict__ bk,
    const float* __restrict__ Wq, const float* __restrict__ bq,
    const float* __restrict__ Wv, const float* __restrict__ bv,
    const float* __restrict__ Ws, const float* __restrict__ bs,
    const float* __restrict__ eatt,
    const float* __restrict__ We1, const float* __restrict__ be1,
    const float* __restrict__ We2, const float* __restrict__ be2,
    int N, int E)
{
    __shared__ __align__(16) float sbuf[5376];

    int tid  = threadIdx.x;
    int lane = tid & 31;
    int wid  = tid >> 5;

    if (blockIdx.x < NODEB) {
        // ================= node GEMM: warp pair per node ====================
        int pr = wid >> 1;
        int r  = wid & 1;

        if (blockIdx.x == 0) {
            for (int i = tid; i < NGRP * 5; i += 256) { g_gsum[i] = 0.f; g_gsq[i] = 0.f; }
            if (tid < NGRP) g_gcnt[tid] = 0.f;
            if (tid == 0)   g_bar = 0u;
        }

        for (int i = tid; i < 256 * 20; i += 256) {
            int c = i / 20, h = i % 20;
            float v;
            if (h < 5)       v = Wk[c * 5 + h];
            else if (h < 10) v = Wq[c * 5 + h - 5];
            else if (h < 15) v = Wv[c * 5 + h - 10];
            else             v = Ws[c * 5 + h - 15];
            sbuf[c * 21 + h] = v;
        }
        __syncthreads();

        unsigned long long w2[40];
#pragma unroll
        for (int i = 0; i < 4; i++) {
            int c = r * 128 + lane * 4 + i;
#pragma unroll
            for (int p = 0; p < 10; p++)
                w2[i * 10 + p] = pack2(sbuf[c * 21 + 2 * p], sbuf[c * 21 + 2 * p + 1]);
        }
        __syncthreads();                          // weights consumed: reuse sbuf

        float blane = 0.f;
        if (lane < 5)       blane = __ldg(&bk[lane]);
        else if (lane < 10) blane = __ldg(&bq[lane - 5]);
        else if (lane < 15) blane = __ldg(&bv[lane - 10]);
        else if (lane < 20) blane = __ldg(&bs[lane - 15]);

        // per pair: two 320-float reduce bufs (16 lanes x 20) + 2x20 handoff
        float* myred = &sbuf[pr * 704 + r * 320];
        float* hbuf  = &sbuf[pr * 704 + 640];
        int bar_id = pr + 1;

        float* kq = (float*)g_kqvv;
        float* ag = (float*)g_aggv;

        int n    = blockIdx.x * 4 + pr;
        int step = NODEB * 4;
        int itp  = 0;

        float4 a0;
        if (n < N)
            a0 = __ldg((const float4*)(x + (size_t)n * 256 + r * 128 + lane * 4));

        while (n < N) {
            float4 cx = a0;
            int nn = n + step;
            if (nn < N)
                a0 = __ldg((const float4*)(x + (size_t)nn * 256 + r * 128 + lane * 4));

            unsigned long long acc2[10];
#pragma unroll
            for (int p = 0; p < 10; p++) acc2[p] = 0ull;

            float xv[4] = {cx.x, cx.y, cx.z, cx.w};
#pragma unroll
            for (int i = 0; i < 4; i++) {
                unsigned long long xa = pack2(xv[i], xv[i]);
#pragma unroll
                for (int p = 0; p < 10; p++)
                    fma2(acc2[p], xa, w2[i * 10 + p]);
            }

            // 1-level butterfly: lanes l and l+16 combine -> 16 partial sets
#pragma unroll
            for (int p = 0; p < 10; p++)
                acc2[p] = add2(acc2[p],
                               __shfl_xor_sync(0xffffffffu, acc2[p], 16));

            if (lane < 16) {
                ulonglong2* dst2 = (ulonglong2*)(myred + lane * 20);
#pragma unroll
                for (int q = 0; q < 5; q++)
                    dst2[q] = make_ulonglong2(acc2[2 * q], acc2[2 * q + 1]);
            }
            __syncwarp();

            float redsum = 0.f;
            if (lane < 20) {
                float s0 = 0.f, s1 = 0.f;
#pragma unroll
                for (int l = 0; l < 16; l += 2) {
                    s0 += myred[(l + 0) * 20 + lane];
                    s1 += myred[(l + 1) * 20 + lane];
                }
                redsum = s0 + s1;
                if (r == 1) hbuf[itp * 20 + lane] = redsum;
            }
            asm volatile("bar.sync %0, %1;" :: "r"(bar_id), "r"(64) : "memory");

            if (r == 0 && lane < 20) {
                float val = redsum + hbuf[itp * 20 + lane] + blane;
                if (lane < 5)        kq[(size_t)n * 32 + lane] = val;
                else if (lane < 10)  kq[(size_t)n * 32 + 8 + 2 * (lane - 5)] = val;
                else if (lane < 15)  kq[(size_t)n * 32 + 9 + 2 * (lane - 10)] = val;
                else                 ag[(size_t)n * 8 + (lane - 15)] = val;
            }
            itp ^= 1;
            n = nn;
        }
    } else {
        // ===== edge GEMV: 4 lanes/edge, 2 edges/iter, cross-iter prefetch ===
        int c   = tid & 3;
        int grp = (tid >> 2) & 7;

        unsigned long long w01[8], w23[8], w4e[8];
#pragma unroll
        for (int i = 0; i < 8; i++) {
            int col = c * 8 + i;
            w01[i] = pack2(__ldg(&We1[col * 5 + 0]), __ldg(&We1[col * 5 + 1]));
            w23[i] = pack2(__ldg(&We1[col * 5 + 2]), __ldg(&We1[col * 5 + 3]));
            w4e[i] = pack2(__ldg(&We1[col * 5 + 4]), __ldg(&We2[col]));
        }
        float b0 = __ldg(&be1[0]), b1 = __ldg(&be1[1]), b2 = __ldg(&be1[2]);
        float b3 = __ldg(&be1[3]), b4 = __ldg(&be1[4]);
        float bec2 = __ldg(be2);

        const float4* ea4 = (const float4*)eatt;
        const int WTOT  = GEMVB * 8;
        const int estep = 2 * WTOT * 8;
        int wg = (blockIdx.x - NODEB) * 8 + wid;

        int ew = wg * 8;
        float4 a0, a1, q0, q1;
        if (ew < E) {
            int eA = ew + grp;
            int eB = ew + WTOT * 8 + grp;
            size_t iA = (size_t)(eA < E ? eA : 0);
            size_t iB = (size_t)(eB < E ? eB : 0);
            a0 = __ldg(&ea4[iA * 8 + c * 2]);
            a1 = __ldg(&ea4[iA * 8 + c * 2 + 1]);
            q0 = __ldg(&ea4[iB * 8 + c * 2]);
            q1 = __ldg(&ea4[iB * 8 + c * 2 + 1]);
        }

        while (ew < E) {
            int ewn = ew + estep;
            float4 na0, na1, nq0, nq1;
            if (ewn < E) {
                int eA = ewn + grp;
                int eB = ewn + WTOT * 8 + grp;
                size_t iA = (size_t)(eA < E ? eA : 0);
                size_t iB = (size_t)(eB < E ? eB : 0);
                na0 = __ldg(&ea4[iA * 8 + c * 2]);
                na1 = __ldg(&ea4[iA * 8 + c * 2 + 1]);
                nq0 = __ldg(&ea4[iB * 8 + c * 2]);
                nq1 = __ldg(&ea4[iB * 8 + c * 2 + 1]);
            }

            int eA = ew + grp;
            int eB = ew + WTOT * 8 + grp;
            bool vA = eA < E, vB = eB < E;

            unsigned long long pA01 = 0ull, pA23 = 0ull, pA4e = 0ull;
            unsigned long long pB01 = 0ull, pB23 = 0ull, pB4e = 0ull;
            float xsA[8] = {a0.x, a0.y, a0.z, a0.w, a1.x, a1.y, a1.z, a1.w};
            float xsB[8] = {q0.x, q0.y, q0.z, q0.w, q1.x, q1.y, q1.z, q1.w};
#pragma unroll
            for (int i = 0; i < 8; i++) {
                unsigned long long xa = pack2(xsA[i], xsA[i]);
                unsigned long long xb = pack2(xsB[i], xsB[i]);
                fma2(pA01, xa, w01[i]); fma2(pA23, xa, w23[i]); fma2(pA4e, xa, w4e[i]);
                fma2(pB01, xb, w01[i]); fma2(pB23, xb, w23[i]); fma2(pB4e, xb, w4e[i]);
            }
#pragma unroll
            for (int off = 2; off > 0; off >>= 1) {
                pA01 = add2(pA01, __shfl_xor_sync(0xffffffffu, pA01, off, 4));
                pA23 = add2(pA23, __shfl_xor_sync(0xffffffffu, pA23, off, 4));
                pA4e = add2(pA4e, __shfl_xor_sync(0xffffffffu, pA4e, off, 4));
                pB01 = add2(pB01, __shfl_xor_sync(0xffffffffu, pB01, off, 4));
                pB23 = add2(pB23, __shfl_xor_sync(0xffffffffu, pB23, off, 4));
                pB4e = add2(pB4e, __shfl_xor_sync(0xffffffffu, pB4e, off, 4));
            }
            float eA0, eA1, eA2, eA3, eA4, eAc2;
            unpack2(pA01, eA0, eA1); unpack2(pA23, eA2, eA3); unpack2(pA4e, eA4, eAc2);
            float eB0, eB1, eB2, eB3, eB4, eBc2;
            unpack2(pB01, eB0, eB1); unpack2(pB23, eB2, eB3); unpack2(pB4e, eB4, eBc2);

            if (vA) {
                if (c == 0)      g_e1a[eA] = make_float4(eA0 + b0, eA1 + b1, eA2 + b2, eA3 + b3);
                else if (c == 1) g_e1b[eA] = eA4 + b4;
                else if (c == 2) g_e2[eA]  = eAc2 + bec2;
            }
            if (vB) {
                if (c == 0)      g_e1a[eB] = make_float4(eB0 + b0, eB1 + b1, eB2 + b2, eB3 + b3);
                else if (c == 1) g_e1b[eB] = eB4 + b4;
                else if (c == 2) g_e2[eB]  = eBc2 + bec2;
            }

            a0 = na0; a1 = na1; q0 = nq0; q1 = nq1;
            ew = ewn;
        }
    }
}

// ---------------------------------------------------------------------------
__device__ __forceinline__ void grid_barrier(unsigned target)
{
    __syncthreads();
    if (threadIdx.x == 0) {
        __threadfence();
        atomicAdd(&g_bar, 1u);
        while (*(volatile unsigned*)&g_bar < target) { }
        __threadfence();
    }
    __syncthreads();
}

// ---------------------------------------------------------------------------
// K2: fused tail — conv1 gate+aggregate -> gnorm stats -> A,B ->
// norm+relu+proj2 -> edge pass2 -> final sigmoid, separated by grid barriers.
__global__ __launch_bounds__(NT3) void fused_tail(
    const int* __restrict__ batch, const int* __restrict__ ei,
    const float* __restrict__ gw, const float* __restrict__ gb,
    const float* __restrict__ gms,
    const float* __restrict__ Wk2, const float* __restrict__ bk2,
    const float* __restrict__ Wq2, const float* __restrict__ bq2,
    const float* __restrict__ Wv2, const float* __restrict__ bv2,
    const float* __restrict__ Ws2, const float* __restrict__ b2,
    float* __restrict__ out, int N, int E)
{
    __shared__ float ssum[NGRP * 5], ssq[NGRP * 5], scnt[NGRP];
    __shared__ float sA[NGRP * 5], sB[NGRP * 5];

    int tid  = threadIdx.x;
    int lane = tid & 31;
    const float* agf = (const float*)g_aggv;
    const float* kqf = (const float*)g_kqvv;
    float*       agw = (float*)g_aggv;

    // ---- phase 0: conv1 gate + aggregate (1 thread/edge, 2 edges/iter) -----
    {
        int base = blockIdx.x * NT3 + tid;
        for (int e = base; e < E; e += 2 * GS3) {
            int eb = e + GS3;
            bool vB = eb < E;
            size_t iB = (size_t)(vB ? eb : 0);

            int sA_ = __ldg(&ei[e]),  dA = __ldg(&ei[E + e]);
            int sB_ = __ldg(&ei[iB]), dB = __ldg(&ei[E + iB]);

            float4 eA03 = __ldg(&g_e1a[e]);
            float  eA4  = __ldg(&g_e1b[e]);
            float4 eB03 = __ldg(&g_e1a[iB]);
            float  eB4  = __ldg(&g_e1b[iB]);

            float4 kAa = __ldg((const float4*)(kqf + (size_t)dA * 32));
            float  kA4 = __ldg(kqf + (size_t)dA * 32 + 4);
            float4 qA0 = __ldg((const float4*)(kqf + (size_t)sA_ * 32 + 8));
            float4 qA1 = __ldg((const float4*)(kqf + (size_t)sA_ * 32 + 12));
            float2 qA2 = __ldg((const float2*)(kqf + (size_t)sA_ * 32 + 16));

            float4 kBa = __ldg((const float4*)(kqf + (size_t)dB * 32));
            float  kB4 = __ldg(kqf + (size_t)dB * 32 + 4);
            float4 qB0 = __ldg((const float4*)(kqf + (size_t)sB_ * 32 + 8));
            float4 qB1 = __ldg((const float4*)(kqf + (size_t)sB_ * 32 + 12));
            float2 qB2 = __ldg((const float2*)(kqf + (size_t)sB_ * 32 + 16));

            {
                float m0 = fast_sigmoid(kAa.x + qA0.x + 2.f * eA03.x) * (qA0.y + eA03.x);
                float m1 = fast_sigmoid(kAa.y + qA0.z + 2.f * eA03.y) * (qA0.w + eA03.y);
                float m2 = fast_sigmoid(kAa.z + qA1.x + 2.f * eA03.z) * (qA1.y + eA03.z);
                float m3 = fast_sigmoid(kAa.w + qA1.z + 2.f * eA03.w) * (qA1.w + eA03.w);
                float m4 = fast_sigmoid(kA4   + qA2.x + 2.f * eA4)    * (qA2.y + eA4);
                atomicAdd(&g_aggv[(size_t)dA * 2], make_float4(m0, m1, m2, m3));
                atomicAdd(&agw[(size_t)dA * 8 + 4], m4);
            }
            if (vB) {
                float m0 = fast_sigmoid(kBa.x + qB0.x + 2.f * eB03.x) * (qB0.y + eB03.x);
                float m1 = fast_sigmoid(kBa.y + qB0.z + 2.f * eB03.y) * (qB0.w + eB03.y);
                float m2 = fast_sigmoid(kBa.z + qB1.x + 2.f * eB03.z) * (qB1.y + eB03.z);
                float m3 = fast_sigmoid(kBa.w + qB1.z + 2.f * eB03.w) * (qB1.w + eB03.w);
                float m4 = fast_sigmoid(kB4   + qB2.x + 2.f * eB4)    * (qB2.y + eB4);
                atomicAdd(&g_aggv[(size_t)dB * 2], make_float4(m0, m1, m2, m3));
                atomicAdd(&agw[(size_t)dB * 8 + 4], m4);
            }
        }
    }

    grid_barrier(1u * NB3);

    // ---- phase 1: group statistics -----------------------------------------
    for (int i = tid; i < NGRP * 5; i += NT3) { ssum[i] = 0.f; ssq[i] = 0.f; }
    if (tid < NGRP) scnt[tid] = 0.f;
    __syncthreads();

#pragma unroll
    for (int it = 0; it < 2; it++) {
        int n = blockIdx.x * NT3 + tid + it * GS3;
        bool valid = n < N;
        unsigned act = __ballot_sync(0xffffffffu, valid);
        if (act == 0) continue;

        int g  = valid ? __ldg(&batch[n]) : 0;
        int g0 = __shfl_sync(0xffffffffu, g, 0);
        bool uni = __all_sync(0xffffffffu, valid && (g == g0));

        float v[5];
        float4 v4 = valid ? __ldcg((const float4*)(agf + (size_t)n * 8))
                          : make_float4(0.f, 0.f, 0.f, 0.f);
        float  v5 = valid ? __ldcg(agf + (size_t)n * 8 + 4) : 0.f;
        v[0] = v4.x; v[1] = v4.y; v[2] = v4.z; v[3] = v4.w; v[4] = v5;

        if (uni) {
#pragma unroll
            for (int h = 0; h < 5; h++) {
                float sv = v[h], sq = v[h] * v[h];
#pragma unroll
                for (int off = 16; off > 0; off >>= 1) {
                    sv += __shfl_xor_sync(0xffffffffu, sv, off);
                    sq += __shfl_xor_sync(0xffffffffu, sq, off);
                }
                if (lane == 0) {
                    atomicAdd(&ssum[g0 * 5 + h], sv);
                    atomicAdd(&ssq[g0 * 5 + h], sq);
                }
            }
            if (lane == 0) atomicAdd(&scnt[g0], 32.f);
        } else if (valid) {
#pragma unroll
            for (int h = 0; h < 5; h++) {
                atomicAdd(&ssum[g * 5 + h], v[h]);
                atomicAdd(&ssq[g * 5 + h], v[h] * v[h]);
            }
            atomicAdd(&scnt[g], 1.f);
        }
    }
    __syncthreads();
    for (int i = tid; i < NGRP * 5; i += NT3) {
        atomicAdd(&g_gsum[i], ssum[i]);
        atomicAdd(&g_gsq[i],  ssq[i]);
    }
    if (tid < NGRP) atomicAdd(&g_gcnt[tid], scnt[tid]);

    grid_barrier(2u * NB3);

    // ---- phase 2: per-group affine ------------------------------------------
    if (tid < NGRP * 5) {
        int g = tid / 5, h = tid % 5;
        float cnt  = fmaxf(__ldcg(&g_gcnt[g]), 1.f);
        float mean = __ldcg(&g_gsum[tid]) / cnt;
        float ex2  = __ldcg(&g_gsq[tid])  / cnt;
        float ms   = __ldg(&gms[h]);
        float d    = mean * ms;
        float var  = ex2 - 2.f * d * mean + d * d;
        float inv  = rsqrtf(var + 1e-5f);
        float wv   = __ldg(&gw[h]);
        sA[tid] = wv * inv;
        sB[tid] = __ldg(&gb[h]) - wv * inv * d;
    }
    __syncthreads();

    // ---- phase 3: norm + relu + conv2 node projections ----------------------
    float k2b = __ldg(bk2), q2b = __ldg(bq2), v2b = __ldg(bv2), s2b = __ldg(b2);
    float wk[5], wq[5], wv5[5], wsk[5];
#pragma unroll
    for (int h = 0; h < 5; h++) {
        wk[h]  = __ldg(&Wk2[h]); wq[h]  = __ldg(&Wq2[h]);
        wv5[h] = __ldg(&Wv2[h]); wsk[h] = __ldg(&Ws2[h]);
    }
#pragma unroll
    for (int it = 0; it < 2; it++) {
        int n = blockIdx.x * NT3 + tid + it * GS3;
        if (n < N) {
            int g = __ldg(&batch[n]);
            float4 a4 = __ldcg((const float4*)(agf + (size_t)n * 8));
            float  a5 = __ldcg(agf + (size_t)n * 8 + 4);
            float av[5] = {a4.x, a4.y, a4.z, a4.w, a5};
            float k2 = k2b, q2 = q2b, v2 = v2b, s2 = s2b;
#pragma unroll
            for (int h = 0; h < 5; h++) {
                float hv = fmaxf(fmaf(sA[g * 5 + h], av[h], sB[g * 5 + h]), 0.f);
                k2 = fmaf(hv, wk[h],  k2);
                q2 = fmaf(hv, wq[h],  q2);
                v2 = fmaf(hv, wv5[h], v2);
                s2 = fmaf(hv, wsk[h], s2);
            }
            g_kqv2[n] = make_float4(k2, q2, v2, 0.f);
            out[n]    = s2;
        }
    }

    grid_barrier(3u * NB3);

    // ---- phase 4: conv2 edge pass (2-wide for MLP) ---------------------------
    {
        int base = blockIdx.x * NT3 + tid;
        for (int e = base; e < E; e += 2 * GS3) {
            int eb = e + GS3;
            bool hb = eb < E;
            int sa = __ldg(&ei[e]),  da = __ldg(&ei[E + e]);
            int sb = hb ? __ldg(&ei[eb]) : 0;
            int db = hb ? __ldg(&ei[E + eb]) : 0;
            float eva = __ldg(&g_e2[e]);
            float evb = hb ? __ldg(&g_e2[eb]) : 0.f;
            float4 da4 = __ldcg(&g_kqv2[da]);
            float4 sa4 = __ldcg(&g_kqv2[sa]);
            float4 db4 = hb ? __ldcg(&g_kqv2[db]) : make_float4(0, 0, 0, 0);
            float4 sb4 = hb ? __ldcg(&g_kqv2[sb]) : make_float4(0, 0, 0, 0);
            float ga = fast_sigmoid(da4.x + sa4.y + 2.f * eva);
            atomicAdd(&out[da], ga * (sa4.z + eva));
            if (hb) {
                float gbv = fast_sigmoid(db4.x + sb4.y + 2.f * evb);
                atomicAdd(&out[db], gbv * (sb4.z + evb));
            }
        }
    }

    grid_barrier(4u * NB3);

    // ---- phase 5: final sigmoid ----------------------------------------------
#pragma unroll
    for (int it = 0; it < 2; it++) {
        int n = blockIdx.x * NT3 + tid + it * GS3;
        if (n < N) out[n] = fast_sigmoid(__ldcg(&out[n]));
    }
}

// ---------------------------------------------------------------------------
extern "C" void kernel_launch(void* const* d_in, const int* in_sizes, int n_in,
                              void* d_out, int out_size)
{
    const float* x     = (const float*)d_in[0];
    const float* eatt  = (const float*)d_in[1];
    const int*   ei    = (const int*)d_in[2];
    const int*   batch = (const int*)d_in[3];
    const float* Wk1 = (const float*)d_in[4];
    const float* bk1 = (const float*)d_in[5];
    const float* Wq1 = (const float*)d_in[6];
    const float* bq1 = (const float*)d_in[7];
    const float* Wv1 = (const float*)d_in[8];
    const float* bv1 = (const float*)d_in[9];
    const float* We1 = (const float*)d_in[10];
    const float* be1 = (const float*)d_in[11];
    const float* Ws1 = (const float*)d_in[12];
    const float* b1  = (const float*)d_in[13];
    const float* gw  = (const float*)d_in[14];
    const float* gb  = (const float*)d_in[15];
    const float* gms = (const float*)d_in[16];
    const float* Wk2 = (const float*)d_in[17];
    const float* bk2 = (const float*)d_in[18];
    const float* Wq2 = (const float*)d_in[19];
    const float* bq2 = (const float*)d_in[20];
    const float* Wv2 = (const float*)d_in[21];
    const float* bv2 = (const float*)d_in[22];
    const float* We2 = (const float*)d_in[23];
    const float* be2 = (const float*)d_in[24];
    const float* Ws2 = (const float*)d_in[25];
    const float* b2  = (const float*)d_in[26];
    float* out = (float*)d_out;

    int N = in_sizes[3];
    int E = in_sizes[2] / 2;
    if (N > NMAX) N = NMAX;
    if (E > EMAX) E = EMAX;

    k1_hetero<<<NODEB + GEMVB, 256>>>(x, Wk1, bk1, Wq1, bq1, Wv1, bv1, Ws1, b1,
                                      eatt, We1, be1, We2, be2, N, E);
    fused_tail<<<NB3, NT3>>>(batch, ei, gw, gb, gms,
                             Wk2, bk2, Wq2, bq2, Wv2, bv2, Ws2, b2,
                             out, N, E);
}

// round 12
// speedup vs baseline: 1.0077x; 1.0077x over previous
#include <cuda_runtime.h>

// ---------------- problem constants ----------------------------------------
#define NMAX 100000
#define EMAX 1600000
#define NGRP 64
#define NODEB 148         // hetero K1: node-GEMM blocks
#define GEMVB 148         // hetero K1: edge-GEMV blocks
#define NB3  148          // fused-tail persistent grid
#define NT3  512
#define GS3  (NB3 * NT3)

// ---------------- scratch (__device__ globals) -----------------------------
__device__ float2   g_kqvv[NMAX * 16];   // per node 32 f: k0..4 @0, (q_s,v_s) @8+2s
__device__ float4   g_aggv[NMAX * 2];    // per node 8 f: conv1 agg in [0..5)
__device__ float4   g_e1a[EMAX];         // per-edge conv1 proj h0..h3 (+bias)
__device__ float    g_e1b[EMAX];         // per-edge conv1 proj h4 (+bias)
__device__ float    g_e2[EMAX];          // per-edge conv2 edge projection (+bias)
__device__ float4   g_kqv2[NMAX];        // conv2 node proj (k2,q2,v2,_)
__device__ float    g_gsum[NGRP * 5];
__device__ float    g_gsq[NGRP * 5];
__device__ float    g_gcnt[NGRP];
__device__ unsigned g_bar;               // grid barrier counter (reset by K1)

// sigmoid via MUFU.TANH: 1 MUFU instead of 2. rel_err ~1e-6, well under 1e-3.
__device__ __forceinline__ float fast_sigmoid(float z) {
    float t;
    asm("tanh.approx.f32 %0, %1;" : "=f"(t) : "f"(z * 0.5f));
    return fmaf(t, 0.5f, 0.5f);
}

// ---- packed f32x2 helpers (ptxas won't emit FFMA2/FADD2 from C++) ---------
__device__ __forceinline__ unsigned long long pack2(float a, float b) {
    unsigned long long r;
    asm("mov.b64 %0, {%1, %2};" : "=l"(r) : "f"(a), "f"(b));
    return r;
}
__device__ __forceinline__ void unpack2(unsigned long long v, float& a, float& b) {
    asm("mov.b64 {%0, %1}, %2;" : "=f"(a), "=f"(b) : "l"(v));
}
__device__ __forceinline__ void fma2(unsigned long long& d,
                                     unsigned long long a, unsigned long long b) {
    asm("fma.rn.f32x2 %0, %1, %2, %0;" : "+l"(d) : "l"(a), "l"(b));
}
__device__ __forceinline__ unsigned long long add2(unsigned long long a,
                                                   unsigned long long b) {
    unsigned long long r;
    asm("add.rn.f32x2 %0, %1, %2;" : "=l"(r) : "l"(a), "l"(b));
    return r;
}

// ---------------------------------------------------------------------------
// K1 (heterogeneous): blocks [0,148) = conv1 node GEMM; blocks [148,296) =
// conv1/conv2 edge-attr GEMV with cross-iteration prefetch. Co-resident
// (2 blocks/SM). Node reduce: 1-level packed butterfly BEFORE the smem
// transpose halves crossbar traffic.
__global__ __launch_bounds__(256, 2) void k1_hetero(
    const float* __restrict__ x,
    const float* __restrict__ Wk, const float* __restrict__ bk,
    const float* __restrict__ Wq, const float* __restrict__ bq,
    const float* __restrict__ Wv, const float* __restrict__ bv,
    const float* __restrict__ Ws, const float* __restrict__ bs,
    const float* __restrict__ eatt,
    const float* __restrict__ We1, const float* __restrict__ be1,
    const float* __restrict__ We2, const float* __restrict__ be2,
    int N, int E)
{
    __shared__ __align__(16) float sbuf[5376];

    int tid  = threadIdx.x;
    int lane = tid & 31;
    int wid  = tid >> 5;

    if (blockIdx.x < NODEB) {
        // ================= node GEMM: warp pair per node ====================
        int pr = wid >> 1;
        int r  = wid & 1;

        if (blockIdx.x == 0) {
            for (int i = tid; i < NGRP * 5; i += 256) { g_gsum[i] = 0.f; g_gsq[i] = 0.f; }
            if (tid < NGRP) g_gcnt[tid] = 0.f;
            if (tid == 0)   g_bar = 0u;
        }

        for (int i = tid; i < 256 * 20; i += 256) {
            int c = i / 20, h = i % 20;
            float v;
            if (h < 5)       v = Wk[c * 5 + h];
            else if (h < 10) v = Wq[c * 5 + h - 5];
            else if (h < 15) v = Wv[c * 5 + h - 10];
            else             v = Ws[c * 5 + h - 15];
            sbuf[c * 21 + h] = v;
        }
        __syncthreads();

        unsigned long long w2[40];
#pragma unroll
        for (int i = 0; i < 4; i++) {
            int c = r * 128 + lane * 4 + i;
#pragma unroll
            for (int p = 0; p < 10; p++)
                w2[i * 10 + p] = pack2(sbuf[c * 21 + 2 * p], sbuf[c * 21 + 2 * p + 1]);
        }
        __syncthreads();                          // weights consumed: reuse sbuf

        float blane = 0.f;
        if (lane < 5)       blane = __ldg(&bk[lane]);
        else if (lane < 10) blane = __ldg(&bq[lane - 5]);
        else if (lane < 15) blane = __ldg(&bv[lane - 10]);
        else if (lane < 20) blane = __ldg(&bs[lane - 15]);

        // per pair: two 320-float reduce bufs (16 lanes x 20) + 2x20 handoff
        float* myred = &sbuf[pr * 704 + r * 320];
        float* hbuf  = &sbuf[pr * 704 + 640];
        int bar_id = pr + 1;

        float* kq = (float*)g_kqvv;
        float* ag = (float*)g_aggv;

        int n    = blockIdx.x * 4 + pr;
        int step = NODEB * 4;
        int itp  = 0;

        float4 a0;
        if (n < N)
            a0 = __ldg((const float4*)(x + (size_t)n * 256 + r * 128 + lane * 4));

        while (n < N) {
            float4 cx = a0;
            int nn = n + step;
            if (nn < N)
                a0 = __ldg((const float4*)(x + (size_t)nn * 256 + r * 128 + lane * 4));

            unsigned long long acc2[10];
#pragma unroll
            for (int p = 0; p < 10; p++) acc2[p] = 0ull;

            float xv[4] = {cx.x, cx.y, cx.z, cx.w};
#pragma unroll
            for (int i = 0; i < 4; i++) {
                unsigned long long xa = pack2(xv[i], xv[i]);
#pragma unroll
                for (int p = 0; p < 10; p++)
                    fma2(acc2[p], xa, w2[i * 10 + p]);
            }

            // 1-level butterfly: lanes l and l+16 combine -> 16 partial sets
#pragma unroll
            for (int p = 0; p < 10; p++)
                acc2[p] = add2(acc2[p],
                               __shfl_xor_sync(0xffffffffu, acc2[p], 16));

            if (lane < 16) {
                ulonglong2* dst2 = (ulonglong2*)(myred + lane * 20);
#pragma unroll
                for (int q = 0; q < 5; q++)
                    dst2[q] = make_ulonglong2(acc2[2 * q], acc2[2 * q + 1]);
            }
            __syncwarp();

            float redsum = 0.f;
            if (lane < 20) {
                float s0 = 0.f, s1 = 0.f;
#pragma unroll
                for (int l = 0; l < 16; l += 2) {
                    s0 += myred[(l + 0) * 20 + lane];
                    s1 += myred[(l + 1) * 20 + lane];
                }
                redsum = s0 + s1;
                if (r == 1) hbuf[itp * 20 + lane] = redsum;
            }
            asm volatile("bar.sync %0, %1;" :: "r"(bar_id), "r"(64) : "memory");

            if (r == 0 && lane < 20) {
                float val = redsum + hbuf[itp * 20 + lane] + blane;
                if (lane < 5)        kq[(size_t)n * 32 + lane] = val;
                else if (lane < 10)  kq[(size_t)n * 32 + 8 + 2 * (lane - 5)] = val;
                else if (lane < 15)  kq[(size_t)n * 32 + 9 + 2 * (lane - 10)] = val;
                else                 ag[(size_t)n * 8 + (lane - 15)] = val;
            }
            itp ^= 1;
            n = nn;
        }
    } else {
        // ===== edge GEMV: 4 lanes/edge, 2 edges/iter, cross-iter prefetch ===
        int c   = tid & 3;
        int grp = (tid >> 2) & 7;

        unsigned long long w01[8], w23[8], w4e[8];
#pragma unroll
        for (int i = 0; i < 8; i++) {
            int col = c * 8 + i;
            w01[i] = pack2(__ldg(&We1[col * 5 + 0]), __ldg(&We1[col * 5 + 1]));
            w23[i] = pack2(__ldg(&We1[col * 5 + 2]), __ldg(&We1[col * 5 + 3]));
            w4e[i] = pack2(__ldg(&We1[col * 5 + 4]), __ldg(&We2[col]));
        }
        float b0 = __ldg(&be1[0]), b1 = __ldg(&be1[1]), b2 = __ldg(&be1[2]);
        float b3 = __ldg(&be1[3]), b4 = __ldg(&be1[4]);
        float bec2 = __ldg(be2);

        const float4* ea4 = (const float4*)eatt;
        const int WTOT  = GEMVB * 8;
        const int estep = 2 * WTOT * 8;
        int wg = (blockIdx.x - NODEB) * 8 + wid;

        int ew = wg * 8;
        float4 a0, a1, q0, q1;
        if (ew < E) {
            int eA = ew + grp;
            int eB = ew + WTOT * 8 + grp;
            size_t iA = (size_t)(eA < E ? eA : 0);
            size_t iB = (size_t)(eB < E ? eB : 0);
            a0 = __ldg(&ea4[iA * 8 + c * 2]);
            a1 = __ldg(&ea4[iA * 8 + c * 2 + 1]);
            q0 = __ldg(&ea4[iB * 8 + c * 2]);
            q1 = __ldg(&ea4[iB * 8 + c * 2 + 1]);
        }

        while (ew < E) {
            int ewn = ew + estep;
            float4 na0, na1, nq0, nq1;
            if (ewn < E) {
                int eA = ewn + grp;
                int eB = ewn + WTOT * 8 + grp;
                size_t iA = (size_t)(eA < E ? eA : 0);
                size_t iB = (size_t)(eB < E ? eB : 0);
                na0 = __ldg(&ea4[iA * 8 + c * 2]);
                na1 = __ldg(&ea4[iA * 8 + c * 2 + 1]);
                nq0 = __ldg(&ea4[iB * 8 + c * 2]);
                nq1 = __ldg(&ea4[iB * 8 + c * 2 + 1]);
            }

            int eA = ew + grp;
            int eB = ew + WTOT * 8 + grp;
            bool vA = eA < E, vB = eB < E;

            unsigned long long pA01 = 0ull, pA23 = 0ull, pA4e = 0ull;
            unsigned long long pB01 = 0ull, pB23 = 0ull, pB4e = 0ull;
            float xsA[8] = {a0.x, a0.y, a0.z, a0.w, a1.x, a1.y, a1.z, a1.w};
            float xsB[8] = {q0.x, q0.y, q0.z, q0.w, q1.x, q1.y, q1.z, q1.w};
#pragma unroll
            for (int i = 0; i < 8; i++) {
                unsigned long long xa = pack2(xsA[i], xsA[i]);
                unsigned long long xb = pack2(xsB[i], xsB[i]);
                fma2(pA01, xa, w01[i]); fma2(pA23, xa, w23[i]); fma2(pA4e, xa, w4e[i]);
                fma2(pB01, xb, w01[i]); fma2(pB23, xb, w23[i]); fma2(pB4e, xb, w4e[i]);
            }
#pragma unroll
            for (int off = 2; off > 0; off >>= 1) {
                pA01 = add2(pA01, __shfl_xor_sync(0xffffffffu, pA01, off, 4));
                pA23 = add2(pA23, __shfl_xor_sync(0xffffffffu, pA23, off, 4));
                pA4e = add2(pA4e, __shfl_xor_sync(0xffffffffu, pA4e, off, 4));
                pB01 = add2(pB01, __shfl_xor_sync(0xffffffffu, pB01, off, 4));
                pB23 = add2(pB23, __shfl_xor_sync(0xffffffffu, pB23, off, 4));
                pB4e = add2(pB4e, __shfl_xor_sync(0xffffffffu, pB4e, off, 4));
            }
            float eA0, eA1, eA2, eA3, eA4, eAc2;
            unpack2(pA01, eA0, eA1); unpack2(pA23, eA2, eA3); unpack2(pA4e, eA4, eAc2);
            float eB0, eB1, eB2, eB3, eB4, eBc2;
            unpack2(pB01, eB0, eB1); unpack2(pB23, eB2, eB3); unpack2(pB4e, eB4, eBc2);

            if (vA) {
                if (c == 0)      g_e1a[eA] = make_float4(eA0 + b0, eA1 + b1, eA2 + b2, eA3 + b3);
                else if (c == 1) g_e1b[eA] = eA4 + b4;
                else if (c == 2) g_e2[eA]  = eAc2 + bec2;
            }
            if (vB) {
                if (c == 0)      g_e1a[eB] = make_float4(eB0 + b0, eB1 + b1, eB2 + b2, eB3 + b3);
                else if (c == 1) g_e1b[eB] = eB4 + b4;
                else if (c == 2) g_e2[eB]  = eBc2 + bec2;
            }

            a0 = na0; a1 = na1; q0 = nq0; q1 = nq1;
            ew = ewn;
        }
    }
}

// ---------------------------------------------------------------------------
// K2: conv1 gate + aggregate. One thread per edge, 2 independent edges/thread,
// full-occupancy grid (latency-bound gathers need maximum warp parallelism).
__global__ __launch_bounds__(256) void gate_agg(const int* __restrict__ ei, int E)
{
    int half = ((E + 511) / 512) * 256;
    int gid  = blockIdx.x * 256 + threadIdx.x;
    if (gid >= half) return;

    const float* kqf = (const float*)g_kqvv;
    float*       agf = (float*)g_aggv;

    int eA = gid;
    int eB = gid + half;
    bool vB = eB < E;
    size_t iB = (size_t)(vB ? eB : 0);

    int sA = __ldg(&ei[eA]), dA = __ldg(&ei[E + eA]);
    int sB = __ldg(&ei[iB]), dB = __ldg(&ei[E + iB]);

    float4 eA03 = __ldg(&g_e1a[eA]);
    float  eA4  = __ldg(&g_e1b[eA]);
    float4 eB03 = __ldg(&g_e1a[iB]);
    float  eB4  = __ldg(&g_e1b[iB]);

    float4 kAa = __ldg((const float4*)(kqf + (size_t)dA * 32));
    float  kA4 = __ldg(kqf + (size_t)dA * 32 + 4);
    float4 qA0 = __ldg((const float4*)(kqf + (size_t)sA * 32 + 8));
    float4 qA1 = __ldg((const float4*)(kqf + (size_t)sA * 32 + 12));
    float2 qA2 = __ldg((const float2*)(kqf + (size_t)sA * 32 + 16));

    float4 kBa = __ldg((const float4*)(kqf + (size_t)dB * 32));
    float  kB4 = __ldg(kqf + (size_t)dB * 32 + 4);
    float4 qB0 = __ldg((const float4*)(kqf + (size_t)sB * 32 + 8));
    float4 qB1 = __ldg((const float4*)(kqf + (size_t)sB * 32 + 12));
    float2 qB2 = __ldg((const float2*)(kqf + (size_t)sB * 32 + 16));

    {
        float m0 = fast_sigmoid(kAa.x + qA0.x + 2.f * eA03.x) * (qA0.y + eA03.x);
        float m1 = fast_sigmoid(kAa.y + qA0.z + 2.f * eA03.y) * (qA0.w + eA03.y);
        float m2 = fast_sigmoid(kAa.z + qA1.x + 2.f * eA03.z) * (qA1.y + eA03.z);
        float m3 = fast_sigmoid(kAa.w + qA1.z + 2.f * eA03.w) * (qA1.w + eA03.w);
        float m4 = fast_sigmoid(kA4   + qA2.x + 2.f * eA4)    * (qA2.y + eA4);
        atomicAdd(&g_aggv[(size_t)dA * 2], make_float4(m0, m1, m2, m3));
        atomicAdd(&agf[(size_t)dA * 8 + 4], m4);
    }
    if (vB) {
        float m0 = fast_sigmoid(kBa.x + qB0.x + 2.f * eB03.x) * (qB0.y + eB03.x);
        float m1 = fast_sigmoid(kBa.y + qB0.z + 2.f * eB03.y) * (qB0.w + eB03.y);
        float m2 = fast_sigmoid(kBa.z + qB1.x + 2.f * eB03.z) * (qB1.y + eB03.z);
        float m3 = fast_sigmoid(kBa.w + qB1.z + 2.f * eB03.w) * (qB1.w + eB03.w);
        float m4 = fast_sigmoid(kB4   + qB2.x + 2.f * eB4)    * (qB2.y + eB4);
        atomicAdd(&g_aggv[(size_t)dB * 2], make_float4(m0, m1, m2, m3));
        atomicAdd(&agf[(size_t)dB * 8 + 4], m4);
    }
}

// ---------------------------------------------------------------------------
__device__ __forceinline__ void grid_barrier(unsigned target)
{
    __syncthreads();
    if (threadIdx.x == 0) {
        __threadfence();
        atomicAdd(&g_bar, 1u);
        while (*(volatile unsigned*)&g_bar < target) { }
        __threadfence();
    }
    __syncthreads();
}

// ---------------------------------------------------------------------------
// K3: fused tail — gnorm stats -> A,B -> norm+relu+proj2 -> edge pass2 ->
// final sigmoid, separated by grid barriers.
__global__ __launch_bounds__(NT3) void fused_tail(
    const int* __restrict__ batch, const int* __restrict__ ei,
    const float* __restrict__ gw, const float* __restrict__ gb,
    const float* __restrict__ gms,
    const float* __restrict__ Wk2, const float* __restrict__ bk2,
    const float* __restrict__ Wq2, const float* __restrict__ bq2,
    const float* __restrict__ Wv2, const float* __restrict__ bv2,
    const float* __restrict__ Ws2, const float* __restrict__ b2,
    float* __restrict__ out, int N, int E)
{
    __shared__ float ssum[NGRP * 5], ssq[NGRP * 5], scnt[NGRP];
    __shared__ float sA[NGRP * 5], sB[NGRP * 5];

    int tid  = threadIdx.x;
    int lane = tid & 31;
    const float* agf = (const float*)g_aggv;

    // ---- phase 1: group statistics -----------------------------------------
    for (int i = tid; i < NGRP * 5; i += NT3) { ssum[i] = 0.f; ssq[i] = 0.f; }
    if (tid < NGRP) scnt[tid] = 0.f;
    __syncthreads();

#pragma unroll
    for (int it = 0; it < 2; it++) {
        int n = blockIdx.x * NT3 + tid + it * GS3;
        bool valid = n < N;
        unsigned act = __ballot_sync(0xffffffffu, valid);
        if (act == 0) continue;

        int g  = valid ? __ldg(&batch[n]) : 0;
        int g0 = __shfl_sync(0xffffffffu, g, 0);
        bool uni = __all_sync(0xffffffffu, valid && (g == g0));

        float v[5];
        float4 v4 = valid ? __ldg((const float4*)(agf + (size_t)n * 8))
                          : make_float4(0.f, 0.f, 0.f, 0.f);
        float  v5 = valid ? __ldg(agf + (size_t)n * 8 + 4) : 0.f;
        v[0] = v4.x; v[1] = v4.y; v[2] = v4.z; v[3] = v4.w; v[4] = v5;

        if (uni) {
#pragma unroll
            for (int h = 0; h < 5; h++) {
                float sv = v[h], sq = v[h] * v[h];
#pragma unroll
                for (int off = 16; off > 0; off >>= 1) {
                    sv += __shfl_xor_sync(0xffffffffu, sv, off);
                    sq += __shfl_xor_sync(0xffffffffu, sq, off);
                }
                if (lane == 0) {
                    atomicAdd(&ssum[g0 * 5 + h], sv);
                    atomicAdd(&ssq[g0 * 5 + h], sq);
                }
            }
            if (lane == 0) atomicAdd(&scnt[g0], 32.f);
        } else if (valid) {
#pragma unroll
            for (int h = 0; h < 5; h++) {
                atomicAdd(&ssum[g * 5 + h], v[h]);
                atomicAdd(&ssq[g * 5 + h], v[h] * v[h]);
            }
            atomicAdd(&scnt[g], 1.f);
        }
    }
    __syncthreads();
    for (int i = tid; i < NGRP * 5; i += NT3) {
        atomicAdd(&g_gsum[i], ssum[i]);
        atomicAdd(&g_gsq[i],  ssq[i]);
    }
    if (tid < NGRP) atomicAdd(&g_gcnt[tid], scnt[tid]);

    grid_barrier(1u * NB3);

    // ---- phase 2: per-group affine ------------------------------------------
    if (tid < NGRP * 5) {
        int g = tid / 5, h = tid % 5;
        float cnt  = fmaxf(__ldcg(&g_gcnt[g]), 1.f);
        float mean = __ldcg(&g_gsum[tid]) / cnt;
        float ex2  = __ldcg(&g_gsq[tid])  / cnt;
        float ms   = __ldg(&gms[h]);
        float d    = mean * ms;
        float var  = ex2 - 2.f * d * mean + d * d;
        float inv  = rsqrtf(var + 1e-5f);
        float wv   = __ldg(&gw[h]);
        sA[tid] = wv * inv;
        sB[tid] = __ldg(&gb[h]) - wv * inv * d;
    }
    __syncthreads();

    // ---- phase 3: norm + relu + conv2 node projections ----------------------
    float k2b = __ldg(bk2), q2b = __ldg(bq2), v2b = __ldg(bv2), s2b = __ldg(b2);
    float wk[5], wq[5], wv5[5], wsk[5];
#pragma unroll
    for (int h = 0; h < 5; h++) {
        wk[h]  = __ldg(&Wk2[h]); wq[h]  = __ldg(&Wq2[h]);
        wv5[h] = __ldg(&Wv2[h]); wsk[h] = __ldg(&Ws2[h]);
    }
#pragma unroll
    for (int it = 0; it < 2; it++) {
        int n = blockIdx.x * NT3 + tid + it * GS3;
        if (n < N) {
            int g = __ldg(&batch[n]);
            float4 a4 = __ldg((const float4*)(agf + (size_t)n * 8));
            float  a5 = __ldg(agf + (size_t)n * 8 + 4);
            float av[5] = {a4.x, a4.y, a4.z, a4.w, a5};
            float k2 = k2b, q2 = q2b, v2 = v2b, s2 = s2b;
#pragma unroll
            for (int h = 0; h < 5; h++) {
                float hv = fmaxf(fmaf(sA[g * 5 + h], av[h], sB[g * 5 + h]), 0.f);
                k2 = fmaf(hv, wk[h],  k2);
                q2 = fmaf(hv, wq[h],  q2);
                v2 = fmaf(hv, wv5[h], v2);
                s2 = fmaf(hv, wsk[h], s2);
            }
            g_kqv2[n] = make_float4(k2, q2, v2, 0.f);
            out[n]    = s2;
        }
    }

    grid_barrier(2u * NB3);

    // ---- phase 4: conv2 edge pass (2-wide for MLP) ---------------------------
    {
        int base = blockIdx.x * NT3 + tid;
        for (int e = base; e < E; e += 2 * GS3) {
            int eb = e + GS3;
            bool hb = eb < E;
            int sa = __ldg(&ei[e]),  da = __ldg(&ei[E + e]);
            int sb = hb ? __ldg(&ei[eb]) : 0;
            int db = hb ? __ldg(&ei[E + eb]) : 0;
            float eva = __ldg(&g_e2[e]);
            float evb = hb ? __ldg(&g_e2[eb]) : 0.f;
            float4 da4 = __ldcg(&g_kqv2[da]);
            float4 sa4 = __ldcg(&g_kqv2[sa]);
            float4 db4 = hb ? __ldcg(&g_kqv2[db]) : make_float4(0, 0, 0, 0);
            float4 sb4 = hb ? __ldcg(&g_kqv2[sb]) : make_float4(0, 0, 0, 0);
            float ga = fast_sigmoid(da4.x + sa4.y + 2.f * eva);
            atomicAdd(&out[da], ga * (sa4.z + eva));
            if (hb) {
                float gbv = fast_sigmoid(db4.x + sb4.y + 2.f * evb);
                atomicAdd(&out[db], gbv * (sb4.z + evb));
            }
        }
    }

    grid_barrier(3u * NB3);

    // ---- phase 5: final sigmoid ----------------------------------------------
#pragma unroll
    for (int it = 0; it < 2; it++) {
        int n = blockIdx.x * NT3 + tid + it * GS3;
        if (n < N) out[n] = fast_sigmoid(__ldcg(&out[n]));
    }
}

// ---------------------------------------------------------------------------
extern "C" void kernel_launch(void* const* d_in, const int* in_sizes, int n_in,
                              void* d_out, int out_size)
{
    const float* x     = (const float*)d_in[0];
    const float* eatt  = (const float*)d_in[1];
    const int*   ei    = (const int*)d_in[2];
    const int*   batch = (const int*)d_in[3];
    const float* Wk1 = (const float*)d_in[4];
    const float* bk1 = (const float*)d_in[5];
    const float* Wq1 = (const float*)d_in[6];
    const float* bq1 = (const float*)d_in[7];
    const float* Wv1 = (const float*)d_in[8];
    const float* bv1 = (const float*)d_in[9];
    const float* We1 = (const float*)d_in[10];
    const float* be1 = (const float*)d_in[11];
    const float* Ws1 = (const float*)d_in[12];
    const float* b1  = (const float*)d_in[13];
    const float* gw  = (const float*)d_in[14];
    const float* gb  = (const float*)d_in[15];
    const float* gms = (const float*)d_in[16];
    const float* Wk2 = (const float*)d_in[17];
    const float* bk2 = (const float*)d_in[18];
    const float* Wq2 = (const float*)d_in[19];
    const float* bq2 = (const float*)d_in[20];
    const float* Wv2 = (const float*)d_in[21];
    const float* bv2 = (const float*)d_in[22];
    const float* We2 = (const float*)d_in[23];
    const float* be2 = (const float*)d_in[24];
    const float* Ws2 = (const float*)d_in[25];
    const float* b2  = (const float*)d_in[26];
    float* out = (float*)d_out;

    int N = in_sizes[3];
    int E = in_sizes[2] / 2;
    if (N > NMAX) N = NMAX;
    if (E > EMAX) E = EMAX;

    int gb2 = (E + 511) / 512;   // gate_agg blocks (2 edges/thread)

    k1_hetero<<<NODEB + GEMVB, 256>>>(x, Wk1, bk1, Wq1, bq1, Wv1, bv1, Ws1, b1,
                                      eatt, We1, be1, We2, be2, N, E);
    gate_agg<<<gb2, 256>>>(ei, E);
    fused_tail<<<NB3, NT3>>>(batch, ei, gw, gb, gms,
                             Wk2, bk2, Wq2, bq2, Wv2, bv2, Ws2, b2,
                             out, N, E);
}

// round 13
// speedup vs baseline: 1.0982x; 1.0898x over previous
#include <cuda_runtime.h>

// ---------------- problem constants ----------------------------------------
#define NMAX 100000
#define EMAX 1600000
#define NGRP 64
#define NODEB 148         // hetero K1: node-GEMM blocks
#define GEMVB 148         // hetero K1: edge-GEMV blocks
#define NB3  148          // fused-tail persistent grid
#define NT3  512
#define GS3  (NB3 * NT3)

// ---------------- scratch (__device__ globals) -----------------------------
// per node 16 floats (64B): [k0..k3][k4,q4,v4,_][q0,v0,q1,v1][q2,v2,q3,v3]
__device__ float4   g_kqv1[NMAX * 4];
__device__ float4   g_aggv[NMAX * 2];    // per node 8 f: conv1 agg in [0..5)
__device__ float4   g_e1a[EMAX];         // per-edge conv1 proj h0..h3 (+bias)
__device__ float    g_e1b[EMAX];         // per-edge conv1 proj h4 (+bias)
__device__ float    g_e2[EMAX];          // per-edge conv2 edge projection (+bias)
__device__ float4   g_kqv2[NMAX];        // conv2 node proj (k2,q2,v2,_)
__device__ float    g_gsum[NGRP * 5];
__device__ float    g_gsq[NGRP * 5];
__device__ float    g_gcnt[NGRP];
__device__ unsigned g_bar;               // grid barrier counter (reset by K1)

// sigmoid via MUFU.TANH: 1 MUFU instead of 2. rel_err ~1e-6, well under 1e-3.
__device__ __forceinline__ float fast_sigmoid(float z) {
    float t;
    asm("tanh.approx.f32 %0, %1;" : "=f"(t) : "f"(z * 0.5f));
    return fmaf(t, 0.5f, 0.5f);
}

// ---- packed f32x2 helpers (ptxas won't emit FFMA2/FADD2 from C++) ---------
__device__ __forceinline__ unsigned long long pack2(float a, float b) {
    unsigned long long r;
    asm("mov.b64 %0, {%1, %2};" : "=l"(r) : "f"(a), "f"(b));
    return r;
}
__device__ __forceinline__ void unpack2(unsigned long long v, float& a, float& b) {
    asm("mov.b64 {%0, %1}, %2;" : "=f"(a), "=f"(b) : "l"(v));
}
__device__ __forceinline__ void fma2(unsigned long long& d,
                                     unsigned long long a, unsigned long long b) {
    asm("fma.rn.f32x2 %0, %1, %2, %0;" : "+l"(d) : "l"(a), "l"(b));
}
__device__ __forceinline__ unsigned long long add2(unsigned long long a,
                                                   unsigned long long b) {
    unsigned long long r;
    asm("add.rn.f32x2 %0, %1, %2;" : "=l"(r) : "l"(a), "l"(b));
    return r;
}

// ---------------------------------------------------------------------------
// K1 (heterogeneous): blocks [0,148) = conv1 node GEMM (R7/R10 reduce — the
// measured optimum); blocks [148,296) = edge-attr GEMV with cross-iteration
// prefetch. Co-resident (2 blocks/SM).
__global__ __launch_bounds__(256, 2) void k1_hetero(
    const float* __restrict__ x,
    const float* __restrict__ Wk, const float* __restrict__ bk,
    const float* __restrict__ Wq, const float* __restrict__ bq,
    const float* __restrict__ Wv, const float* __restrict__ bv,
    const float* __restrict__ Ws, const float* __restrict__ bs,
    const float* __restrict__ eatt,
    const float* __restrict__ We1, const float* __restrict__ be1,
    const float* __restrict__ We2, const float* __restrict__ be2,
    int N, int E)
{
    __shared__ __align__(16) float sbuf[5376];

    int tid  = threadIdx.x;
    int lane = tid & 31;
    int wid  = tid >> 5;

    if (blockIdx.x < NODEB) {
        // ================= node GEMM: warp pair per node ====================
        int pr = wid >> 1;
        int r  = wid & 1;

        if (blockIdx.x == 0) {
            for (int i = tid; i < NGRP * 5; i += 256) { g_gsum[i] = 0.f; g_gsq[i] = 0.f; }
            if (tid < NGRP) g_gcnt[tid] = 0.f;
            if (tid == 0)   g_bar = 0u;
        }

        for (int i = tid; i < 256 * 20; i += 256) {
            int c = i / 20, h = i % 20;
            float v;
            if (h < 5)       v = Wk[c * 5 + h];
            else if (h < 10) v = Wq[c * 5 + h - 5];
            else if (h < 15) v = Wv[c * 5 + h - 10];
            else             v = Ws[c * 5 + h - 15];
            sbuf[c * 21 + h] = v;
        }
        __syncthreads();

        unsigned long long w2[40];
#pragma unroll
        for (int i = 0; i < 4; i++) {
            int c = r * 128 + lane * 4 + i;
#pragma unroll
            for (int p = 0; p < 10; p++)
                w2[i * 10 + p] = pack2(sbuf[c * 21 + 2 * p], sbuf[c * 21 + 2 * p + 1]);
        }
        __syncthreads();                          // weights consumed: reuse sbuf

        float blane = 0.f;
        if (lane < 5)       blane = __ldg(&bk[lane]);
        else if (lane < 10) blane = __ldg(&bq[lane - 5]);
        else if (lane < 15) blane = __ldg(&bv[lane - 10]);
        else if (lane < 20) blane = __ldg(&bs[lane - 15]);

        float* myred = &sbuf[pr * 1320 + r * 640];
        float* hbuf  = &sbuf[pr * 1320 + 1280];   // 2x20 double-buffered handoff
        int bar_id = pr + 1;

        float* kq = (float*)g_kqv1;
        float* ag = (float*)g_aggv;

        int n    = blockIdx.x * 4 + pr;
        int step = NODEB * 4;
        int itp  = 0;

        float4 a0;
        if (n < N)
            a0 = __ldg((const float4*)(x + (size_t)n * 256 + r * 128 + lane * 4));

        while (n < N) {
            float4 cx = a0;
            int nn = n + step;
            if (nn < N)
                a0 = __ldg((const float4*)(x + (size_t)nn * 256 + r * 128 + lane * 4));

            unsigned long long acc2[10];
#pragma unroll
            for (int p = 0; p < 10; p++) acc2[p] = 0ull;

            float xv[4] = {cx.x, cx.y, cx.z, cx.w};
#pragma unroll
            for (int i = 0; i < 4; i++) {
                unsigned long long xa = pack2(xv[i], xv[i]);
#pragma unroll
                for (int p = 0; p < 10; p++)
                    fma2(acc2[p], xa, w2[i * 10 + p]);
            }

            ulonglong2* dst2 = (ulonglong2*)(myred + lane * 20);
#pragma unroll
            for (int q = 0; q < 5; q++)
                dst2[q] = make_ulonglong2(acc2[2 * q], acc2[2 * q + 1]);
            __syncwarp();

            float redsum = 0.f;
            if (lane < 20) {
                float s0 = 0.f, s1 = 0.f;
#pragma unroll
                for (int l = 0; l < 32; l += 2) {
                    s0 += myred[(l + 0) * 20 + lane];
                    s1 += myred[(l + 1) * 20 + lane];
                }
                redsum = s0 + s1;
                if (r == 1) hbuf[itp * 20 + lane] = redsum;
            }
            asm volatile("bar.sync %0, %1;" :: "r"(bar_id), "r"(64) : "memory");

            if (r == 0 && lane < 20) {
                float val = redsum + hbuf[itp * 20 + lane] + blane;
                // compact 16-float row layout
                int idx;
                if (lane < 5) {
                    idx = lane;                                   // k0..k4 @ 0..4
                } else if (lane < 10) {
                    int s = lane - 5;                             // q_s
                    idx = (s < 4) ? (8 + 2 * s) : 5;
                } else if (lane < 15) {
                    int s = lane - 10;                            // v_s
                    idx = (s < 4) ? (9 + 2 * s) : 6;
                } else {
                    ag[(size_t)n * 8 + (lane - 15)] = val;        // skip term
                    idx = -1;
                }
                if (idx >= 0) kq[(size_t)n * 16 + idx] = val;
            }
            itp ^= 1;
            n = nn;
        }
    } else {
        // ===== edge GEMV: 4 lanes/edge, 2 edges/iter, cross-iter prefetch ===
        int c   = tid & 3;
        int grp = (tid >> 2) & 7;

        unsigned long long w01[8], w23[8], w4e[8];
#pragma unroll
        for (int i = 0; i < 8; i++) {
            int col = c * 8 + i;
            w01[i] = pack2(__ldg(&We1[col * 5 + 0]), __ldg(&We1[col * 5 + 1]));
            w23[i] = pack2(__ldg(&We1[col * 5 + 2]), __ldg(&We1[col * 5 + 3]));
            w4e[i] = pack2(__ldg(&We1[col * 5 + 4]), __ldg(&We2[col]));
        }
        float b0 = __ldg(&be1[0]), b1 = __ldg(&be1[1]), b2 = __ldg(&be1[2]);
        float b3 = __ldg(&be1[3]), b4 = __ldg(&be1[4]);
        float bec2 = __ldg(be2);

        const float4* ea4 = (const float4*)eatt;
        const int WTOT  = GEMVB * 8;
        const int estep = 2 * WTOT * 8;
        int wg = (blockIdx.x - NODEB) * 8 + wid;

        int ew = wg * 8;
        float4 a0, a1, q0, q1;
        if (ew < E) {
            int eA = ew + grp;
            int eB = ew + WTOT * 8 + grp;
            size_t iA = (size_t)(eA < E ? eA : 0);
            size_t iB = (size_t)(eB < E ? eB : 0);
            a0 = __ldg(&ea4[iA * 8 + c * 2]);
            a1 = __ldg(&ea4[iA * 8 + c * 2 + 1]);
            q0 = __ldg(&ea4[iB * 8 + c * 2]);
            q1 = __ldg(&ea4[iB * 8 + c * 2 + 1]);
        }

        while (ew < E) {
            int ewn = ew + estep;
            float4 na0, na1, nq0, nq1;
            if (ewn < E) {
                int eA = ewn + grp;
                int eB = ewn + WTOT * 8 + grp;
                size_t iA = (size_t)(eA < E ? eA : 0);
                size_t iB = (size_t)(eB < E ? eB : 0);
                na0 = __ldg(&ea4[iA * 8 + c * 2]);
                na1 = __ldg(&ea4[iA * 8 + c * 2 + 1]);
                nq0 = __ldg(&ea4[iB * 8 + c * 2]);
                nq1 = __ldg(&ea4[iB * 8 + c * 2 + 1]);
            }

            int eA = ew + grp;
            int eB = ew + WTOT * 8 + grp;
            bool vA = eA < E, vB = eB < E;

            unsigned long long pA01 = 0ull, pA23 = 0ull, pA4e = 0ull;
            unsigned long long pB01 = 0ull, pB23 = 0ull, pB4e = 0ull;
            float xsA[8] = {a0.x, a0.y, a0.z, a0.w, a1.x, a1.y, a1.z, a1.w};
            float xsB[8] = {q0.x, q0.y, q0.z, q0.w, q1.x, q1.y, q1.z, q1.w};
#pragma unroll
            for (int i = 0; i < 8; i++) {
                unsigned long long xa = pack2(xsA[i], xsA[i]);
                unsigned long long xb = pack2(xsB[i], xsB[i]);
                fma2(pA01, xa, w01[i]); fma2(pA23, xa, w23[i]); fma2(pA4e, xa, w4e[i]);
                fma2(pB01, xb, w01[i]); fma2(pB23, xb, w23[i]); fma2(pB4e, xb, w4e[i]);
            }
#pragma unroll
            for (int off = 2; off > 0; off >>= 1) {
                pA01 = add2(pA01, __shfl_xor_sync(0xffffffffu, pA01, off, 4));
                pA23 = add2(pA23, __shfl_xor_sync(0xffffffffu, pA23, off, 4));
                pA4e = add2(pA4e, __shfl_xor_sync(0xffffffffu, pA4e, off, 4));
                pB01 = add2(pB01, __shfl_xor_sync(0xffffffffu, pB01, off, 4));
                pB23 = add2(pB23, __shfl_xor_sync(0xffffffffu, pB23, off, 4));
                pB4e = add2(pB4e, __shfl_xor_sync(0xffffffffu, pB4e, off, 4));
            }
            float eA0, eA1, eA2, eA3, eA4, eAc2;
            unpack2(pA01, eA0, eA1); unpack2(pA23, eA2, eA3); unpack2(pA4e, eA4, eAc2);
            float eB0, eB1, eB2, eB3, eB4, eBc2;
            unpack2(pB01, eB0, eB1); unpack2(pB23, eB2, eB3); unpack2(pB4e, eB4, eBc2);

            if (vA) {
                if (c == 0)      g_e1a[eA] = make_float4(eA0 + b0, eA1 + b1, eA2 + b2, eA3 + b3);
                else if (c == 1) g_e1b[eA] = eA4 + b4;
                else if (c == 2) g_e2[eA]  = eAc2 + bec2;
            }
            if (vB) {
                if (c == 0)      g_e1a[eB] = make_float4(eB0 + b0, eB1 + b1, eB2 + b2, eB3 + b3);
                else if (c == 1) g_e1b[eB] = eB4 + b4;
                else if (c == 2) g_e2[eB]  = eBc2 + bec2;
            }

            a0 = na0; a1 = na1; q0 = nq0; q1 = nq1;
            ew = ewn;
        }
    }
}

// ---------------------------------------------------------------------------
// K2: conv1 gate + aggregate. One thread per edge, 2 independent edges/thread,
// full-occupancy grid. Node rows are 64B: dst needs 2 LDG.128 (one sector),
// src needs 3 LDG.128 (two sectors).
__global__ __launch_bounds__(256) void gate_agg(const int* __restrict__ ei, int E)
{
    int half = ((E + 511) / 512) * 256;
    int gid  = blockIdx.x * 256 + threadIdx.x;
    if (gid >= half) return;

    float* agf = (float*)g_aggv;

    int eA = gid;
    int eB = gid + half;
    bool vB = eB < E;
    size_t iB = (size_t)(vB ? eB : 0);

    int sA = __ldg(&ei[eA]), dA = __ldg(&ei[E + eA]);
    int sB = __ldg(&ei[iB]), dB = __ldg(&ei[E + iB]);

    float4 eA03 = __ldg(&g_e1a[eA]);
    float  eA4  = __ldg(&g_e1b[eA]);
    float4 eB03 = __ldg(&g_e1a[iB]);
    float  eB4  = __ldg(&g_e1b[iB]);

    // dst rows: k0..k3 @ q0, (k4,q4,v4,_) @ q1
    float4 kA03 = __ldg(&g_kqv1[(size_t)dA * 4]);
    float4 kA4  = __ldg(&g_kqv1[(size_t)dA * 4 + 1]);
    // src rows: (k4,q4,v4,_) @ q1, (q0,v0,q1,v1) @ q2, (q2,v2,q3,v3) @ q3
    float4 sA4  = __ldg(&g_kqv1[(size_t)sA * 4 + 1]);
    float4 qA01 = __ldg(&g_kqv1[(size_t)sA * 4 + 2]);
    float4 qA23 = __ldg(&g_kqv1[(size_t)sA * 4 + 3]);

    float4 kB03 = __ldg(&g_kqv1[(size_t)dB * 4]);
    float4 kB4  = __ldg(&g_kqv1[(size_t)dB * 4 + 1]);
    float4 sB4  = __ldg(&g_kqv1[(size_t)sB * 4 + 1]);
    float4 qB01 = __ldg(&g_kqv1[(size_t)sB * 4 + 2]);
    float4 qB23 = __ldg(&g_kqv1[(size_t)sB * 4 + 3]);

    {
        float m0 = fast_sigmoid(kA03.x + qA01.x + 2.f * eA03.x) * (qA01.y + eA03.x);
        float m1 = fast_sigmoid(kA03.y + qA01.z + 2.f * eA03.y) * (qA01.w + eA03.y);
        float m2 = fast_sigmoid(kA03.z + qA23.x + 2.f * eA03.z) * (qA23.y + eA03.z);
        float m3 = fast_sigmoid(kA03.w + qA23.z + 2.f * eA03.w) * (qA23.w + eA03.w);
        float m4 = fast_sigmoid(kA4.x  + sA4.y  + 2.f * eA4)    * (sA4.z  + eA4);
        atomicAdd(&g_aggv[(size_t)dA * 2], make_float4(m0, m1, m2, m3));
        atomicAdd(&agf[(size_t)dA * 8 + 4], m4);
    }
    if (vB) {
        float m0 = fast_sigmoid(kB03.x + qB01.x + 2.f * eB03.x) * (qB01.y + eB03.x);
        float m1 = fast_sigmoid(kB03.y + qB01.z + 2.f * eB03.y) * (qB01.w + eB03.y);
        float m2 = fast_sigmoid(kB03.z + qB23.x + 2.f * eB03.z) * (qB23.y + eB03.z);
        float m3 = fast_sigmoid(kB03.w + qB23.z + 2.f * eB03.w) * (qB23.w + eB03.w);
        float m4 = fast_sigmoid(kB4.x  + sB4.y  + 2.f * eB4)    * (sB4.z  + eB4);
        atomicAdd(&g_aggv[(size_t)dB * 2], make_float4(m0, m1, m2, m3));
        atomicAdd(&agf[(size_t)dB * 8 + 4], m4);
    }
}

// ---------------------------------------------------------------------------
__device__ __forceinline__ void grid_barrier(unsigned target)
{
    __syncthreads();
    if (threadIdx.x == 0) {
        __threadfence();
        atomicAdd(&g_bar, 1u);
        while (*(volatile unsigned*)&g_bar < target) { }
        __threadfence();
    }
    __syncthreads();
}

// ---------------------------------------------------------------------------
// K3: fused tail — gnorm stats -> A,B -> norm+relu+proj2 -> edge pass2 ->
// final sigmoid, separated by grid barriers.
__global__ __launch_bounds__(NT3) void fused_tail(
    const int* __restrict__ batch, const int* __restrict__ ei,
    const float* __restrict__ gw, const float* __restrict__ gb,
    const float* __restrict__ gms,
    const float* __restrict__ Wk2, const float* __restrict__ bk2,
    const float* __restrict__ Wq2, const float* __restrict__ bq2,
    const float* __restrict__ Wv2, const float* __restrict__ bv2,
    const float* __restrict__ Ws2, const float* __restrict__ b2,
    float* __restrict__ out, int N, int E)
{
    __shared__ float ssum[NGRP * 5], ssq[NGRP * 5], scnt[NGRP];
    __shared__ float sA[NGRP * 5], sB[NGRP * 5];

    int tid  = threadIdx.x;
    int lane = tid & 31;
    const float* agf = (const float*)g_aggv;

    // ---- phase 1: group statistics -----------------------------------------
    for (int i = tid; i < NGRP * 5; i += NT3) { ssum[i] = 0.f; ssq[i] = 0.f; }
    if (tid < NGRP) scnt[tid] = 0.f;
    __syncthreads();

#pragma unroll
    for (int it = 0; it < 2; it++) {
        int n = blockIdx.x * NT3 + tid + it * GS3;
        bool valid = n < N;
        unsigned act = __ballot_sync(0xffffffffu, valid);
        if (act == 0) continue;

        int g  = valid ? __ldg(&batch[n]) : 0;
        int g0 = __shfl_sync(0xffffffffu, g, 0);
        bool uni = __all_sync(0xffffffffu, valid && (g == g0));

        float v[5];
        float4 v4 = valid ? __ldg((const float4*)(agf + (size_t)n * 8))
                          : make_float4(0.f, 0.f, 0.f, 0.f);
        float  v5 = valid ? __ldg(agf + (size_t)n * 8 + 4) : 0.f;
        v[0] = v4.x; v[1] = v4.y; v[2] = v4.z; v[3] = v4.w; v[4] = v5;

        if (uni) {
#pragma unroll
            for (int h = 0; h < 5; h++) {
                float sv = v[h], sq = v[h] * v[h];
#pragma unroll
                for (int off = 16; off > 0; off >>= 1) {
                    sv += __shfl_xor_sync(0xffffffffu, sv, off);
                    sq += __shfl_xor_sync(0xffffffffu, sq, off);
                }
                if (lane == 0) {
                    atomicAdd(&ssum[g0 * 5 + h], sv);
                    atomicAdd(&ssq[g0 * 5 + h], sq);
                }
            }
            if (lane == 0) atomicAdd(&scnt[g0], 32.f);
        } else if (valid) {
#pragma unroll
            for (int h = 0; h < 5; h++) {
                atomicAdd(&ssum[g * 5 + h], v[h]);
                atomicAdd(&ssq[g * 5 + h], v[h] * v[h]);
            }
            atomicAdd(&scnt[g], 1.f);
        }
    }
    __syncthreads();
    for (int i = tid; i < NGRP * 5; i += NT3) {
        atomicAdd(&g_gsum[i], ssum[i]);
        atomicAdd(&g_gsq[i],  ssq[i]);
    }
    if (tid < NGRP) atomicAdd(&g_gcnt[tid], scnt[tid]);

    grid_barrier(1u * NB3);

    // ---- phase 2: per-group affine ------------------------------------------
    if (tid < NGRP * 5) {
        int g = tid / 5, h = tid % 5;
        float cnt  = fmaxf(__ldcg(&g_gcnt[g]), 1.f);
        float mean = __ldcg(&g_gsum[tid]) / cnt;
        float ex2  = __ldcg(&g_gsq[tid])  / cnt;
        float ms   = __ldg(&gms[h]);
        float d    = mean * ms;
        float var  = ex2 - 2.f * d * mean + d * d;
        float inv  = rsqrtf(var + 1e-5f);
        float wv   = __ldg(&gw[h]);
        sA[tid] = wv * inv;
        sB[tid] = __ldg(&gb[h]) - wv * inv * d;
    }
    __syncthreads();

    // ---- phase 3: norm + relu + conv2 node projections ----------------------
    float k2b = __ldg(bk2), q2b = __ldg(bq2), v2b = __ldg(bv2), s2b = __ldg(b2);
    float wk[5], wq[5], wv5[5], wsk[5];
#pragma unroll
    for (int h = 0; h < 5; h++) {
        wk[h]  = __ldg(&Wk2[h]); wq[h]  = __ldg(&Wq2[h]);
        wv5[h] = __ldg(&Wv2[h]); wsk[h] = __ldg(&Ws2[h]);
    }
#pragma unroll
    for (int it = 0; it < 2; it++) {
        int n = blockIdx.x * NT3 + tid + it * GS3;
        if (n < N) {
            int g = __ldg(&batch[n]);
            float4 a4 = __ldg((const float4*)(agf + (size_t)n * 8));
            float  a5 = __ldg(agf + (size_t)n * 8 + 4);
            float av[5] = {a4.x, a4.y, a4.z, a4.w, a5};
            float k2 = k2b, q2 = q2b, v2 = v2b, s2 = s2b;
#pragma unroll
            for (int h = 0; h < 5; h++) {
                float hv = fmaxf(fmaf(sA[g * 5 + h], av[h], sB[g * 5 + h]), 0.f);
                k2 = fmaf(hv, wk[h],  k2);
                q2 = fmaf(hv, wq[h],  q2);
                v2 = fmaf(hv, wv5[h], v2);
                s2 = fmaf(hv, wsk[h], s2);
            }
            g_kqv2[n] = make_float4(k2, q2, v2, 0.f);
            out[n]    = s2;
        }
    }

    grid_barrier(2u * NB3);

    // ---- phase 4: conv2 edge pass (2-wide for MLP) ---------------------------
    {
        int base = blockIdx.x * NT3 + tid;
        for (int e = base; e < E; e += 2 * GS3) {
            int eb = e + GS3;
            bool hb = eb < E;
            int sa = __ldg(&ei[e]),  da = __ldg(&ei[E + e]);
            int sb = hb ? __ldg(&ei[eb]) : 0;
            int db = hb ? __ldg(&ei[E + eb]) : 0;
            float eva = __ldg(&g_e2[e]);
            float evb = hb ? __ldg(&g_e2[eb]) : 0.f;
            float4 da4 = __ldcg(&g_kqv2[da]);
            float4 sa4 = __ldcg(&g_kqv2[sa]);
            float4 db4 = hb ? __ldcg(&g_kqv2[db]) : make_float4(0, 0, 0, 0);
            float4 sb4 = hb ? __ldcg(&g_kqv2[sb]) : make_float4(0, 0, 0, 0);
            float ga = fast_sigmoid(da4.x + sa4.y + 2.f * eva);
            atomicAdd(&out[da], ga * (sa4.z + eva));
            if (hb) {
                float gbv = fast_sigmoid(db4.x + sb4.y + 2.f * evb);
                atomicAdd(&out[db], gbv * (sb4.z + evb));
            }
        }
    }

    grid_barrier(3u * NB3);

    // ---- phase 5: final sigmoid ----------------------------------------------
#pragma unroll
    for (int it = 0; it < 2; it++) {
        int n = blockIdx.x * NT3 + tid + it * GS3;
        if (n < N) out[n] = fast_sigmoid(__ldcg(&out[n]));
    }
}

// ---------------------------------------------------------------------------
extern "C" void kernel_launch(void* const* d_in, const int* in_sizes, int n_in,
                              void* d_out, int out_size)
{
    const float* x     = (const float*)d_in[0];
    const float* eatt  = (const float*)d_in[1];
    const int*   ei    = (const int*)d_in[2];
    const int*   batch = (const int*)d_in[3];
    const float* Wk1 = (const float*)d_in[4];
    const float* bk1 = (const float*)d_in[5];
    const float* Wq1 = (const float*)d_in[6];
    const float* bq1 = (const float*)d_in[7];
    const float* Wv1 = (const float*)d_in[8];
    const float* bv1 = (const float*)d_in[9];
    const float* We1 = (const float*)d_in[10];
    const float* be1 = (const float*)d_in[11];
    const float* Ws1 = (const float*)d_in[12];
    const float* b1  = (const float*)d_in[13];
    const float* gw  = (const float*)d_in[14];
    const float* gb  = (const float*)d_in[15];
    const float* gms = (const float*)d_in[16];
    const float* Wk2 = (const float*)d_in[17];
    const float* bk2 = (const float*)d_in[18];
    const float* Wq2 = (const float*)d_in[19];
    const float* bq2 = (const float*)d_in[20];
    const float* Wv2 = (const float*)d_in[21];
    const float* bv2 = (const float*)d_in[22];
    const float* We2 = (const float*)d_in[23];
    const float* be2 = (const float*)d_in[24];
    const float* Ws2 = (const float*)d_in[25];
    const float* b2  = (const float*)d_in[26];
    float* out = (float*)d_out;

    int N = in_sizes[3];
    int E = in_sizes[2] / 2;
    if (N > NMAX) N = NMAX;
    if (E > EMAX) E = EMAX;

    int gb2 = (E + 511) / 512;   // gate_agg blocks (2 edges/thread)

    k1_hetero<<<NODEB + GEMVB, 256>>>(x, Wk1, bk1, Wq1, bq1, Wv1, bv1, Ws1, b1,
                                      eatt, We1, be1, We2, be2, N, E);
    gate_agg<<<gb2, 256>>>(ei, E);
    fused_tail<<<NB3, NT3>>>(batch, ei, gw, gb, gms,
                             Wk2, bk2, Wq2, bq2, Wv2, bv2, Ws2, b2,
                             out, N, E);
}

// round 14
// speedup vs baseline: 1.1810x; 1.0754x over previous
#include <cuda_runtime.h>

// ---------------- problem constants ----------------------------------------
#define NMAX 100000
#define EMAX 1600000
#define NGRP 64
#define NB3  148          // fused-tail persistent grid
#define NT3  512
#define GS3  (NB3 * NT3)

// ---------------- scratch (__device__ globals) -----------------------------
// per node 16 floats (64B): [k0..k3][k4,q4,v4,_][q0,v0,q1,v1][q2,v2,q3,v3]
__device__ float4   g_kqv1[NMAX * 4];
__device__ float4   g_aggv[NMAX * 2];    // per node 8 f: conv1 agg in [0..5)
__device__ float4   g_e1a[EMAX];         // per-edge conv1 proj h0..h3 (+bias)
__device__ float    g_e1b[EMAX];         // per-edge conv1 proj h4 (+bias)
__device__ float    g_e2[EMAX];          // per-edge conv2 edge projection (+bias)
__device__ float4   g_kqv2[NMAX];        // conv2 node proj (k2,q2,v2,_)
__device__ float    g_gsum[NGRP * 5];
__device__ float    g_gsq[NGRP * 5];
__device__ float    g_gcnt[NGRP];
__device__ unsigned g_bar;               // grid barrier counter (reset by K1)

// sigmoid via MUFU.TANH: 1 MUFU instead of 2. rel_err ~1e-6, well under 1e-3.
__device__ __forceinline__ float fast_sigmoid(float z) {
    float t;
    asm("tanh.approx.f32 %0, %1;" : "=f"(t) : "f"(z * 0.5f));
    return fmaf(t, 0.5f, 0.5f);
}

// ---- packed f32x2 helpers (ptxas won't emit FFMA2/FADD2 from C++) ---------
__device__ __forceinline__ unsigned long long pack2(float a, float b) {
    unsigned long long r;
    asm("mov.b64 %0, {%1, %2};" : "=l"(r) : "f"(a), "f"(b));
    return r;
}
__device__ __forceinline__ void unpack2(unsigned long long v, float& a, float& b) {
    asm("mov.b64 {%0, %1}, %2;" : "=f"(a), "=f"(b) : "l"(v));
}
__device__ __forceinline__ void fma2(unsigned long long& d,
                                     unsigned long long a, unsigned long long b) {
    asm("fma.rn.f32x2 %0, %1, %2, %0;" : "+l"(d) : "l"(a), "l"(b));
}
__device__ __forceinline__ unsigned long long add2(unsigned long long a,
                                                   unsigned long long b) {
    unsigned long long r;
    asm("add.rn.f32x2 %0, %1, %2;" : "=l"(r) : "l"(a), "l"(b));
    return r;
}

// ---------------------------------------------------------------------------
// K1a: conv1 node GEMM, standalone (the R5 55.9us champion: 1 block/SM,
// warp-per-node, lane holds 8 cols x 10 h-pairs in 80 u64 regs, TWO nodes per
// iteration for ILP, smem transpose reduce).
__global__ __launch_bounds__(256, 1) void node_proj1(
    const float* __restrict__ x,
    const float* __restrict__ Wk, const float* __restrict__ bk,
    const float* __restrict__ Wq, const float* __restrict__ bq,
    const float* __restrict__ Wv, const float* __restrict__ bv,
    const float* __restrict__ Ws, const float* __restrict__ bs,
    int N)
{
    __shared__ __align__(16) float sbuf[10240];   // 40KB, dual-purpose

    int tid  = threadIdx.x;
    int lane = tid & 31;
    int wid  = tid >> 5;

    if (blockIdx.x == 0) {                        // fold zero_stats + bar reset
        for (int i = tid; i < NGRP * 5; i += 256) { g_gsum[i] = 0.f; g_gsq[i] = 0.f; }
        if (tid < NGRP) g_gcnt[tid] = 0.f;
        if (tid == 0)   g_bar = 0u;
    }

    // stage combined weights [c][h] with stride 21
    for (int i = tid; i < 256 * 20; i += 256) {
        int c = i / 20, h = i % 20;
        float v;
        if (h < 5)       v = Wk[c * 5 + h];
        else if (h < 10) v = Wq[c * 5 + h - 5];
        else if (h < 15) v = Wv[c * 5 + h - 10];
        else             v = Ws[c * 5 + h - 15];
        sbuf[c * 21 + h] = v;
    }
    __syncthreads();

    unsigned long long w2[80];
#pragma unroll
    for (int i = 0; i < 8; i++) {
        int c = lane * 8 + i;
#pragma unroll
        for (int p = 0; p < 10; p++)
            w2[i * 10 + p] = pack2(sbuf[c * 21 + 2 * p], sbuf[c * 21 + 2 * p + 1]);
    }
    __syncthreads();                              // weights consumed: reuse sbuf

    float blane = 0.f;
    if (lane < 5)       blane = __ldg(&bk[lane]);
    else if (lane < 10) blane = __ldg(&bq[lane - 5]);
    else if (lane < 15) blane = __ldg(&bv[lane - 10]);
    else if (lane < 20) blane = __ldg(&bs[lane - 15]);

    float* redA = &sbuf[wid * 1280];
    float* redB = redA + 640;
    float* kq   = (float*)g_kqv1;
    float* ag   = (float*)g_aggv;

    int warp = blockIdx.x * 8 + wid;
    int step = gridDim.x * 8 * 2;

    int n = warp * 2;
    float4 a0A, a1A, a0B, a1B;
    if (n < N) {
        const float4* xr = (const float4*)(x + (size_t)n * 256 + lane * 8);
        a0A = __ldg(xr); a1A = __ldg(xr + 1);
    }
    if (n + 1 < N) {
        const float4* xr = (const float4*)(x + (size_t)(n + 1) * 256 + lane * 8);
        a0B = __ldg(xr); a1B = __ldg(xr + 1);
    }

    while (n < N) {
        float4 cA0 = a0A, cA1 = a1A, cB0 = a0B, cB1 = a1B;
        bool hb = (n + 1) < N;
        int nn = n + step;
        if (nn < N) {
            const float4* xr = (const float4*)(x + (size_t)nn * 256 + lane * 8);
            a0A = __ldg(xr); a1A = __ldg(xr + 1);
        }
        if (nn + 1 < N) {
            const float4* xr = (const float4*)(x + (size_t)(nn + 1) * 256 + lane * 8);
            a0B = __ldg(xr); a1B = __ldg(xr + 1);
        }

        unsigned long long accA[10], accB[10];
#pragma unroll
        for (int p = 0; p < 10; p++) { accA[p] = 0ull; accB[p] = 0ull; }

        float xA[8] = {cA0.x, cA0.y, cA0.z, cA0.w, cA1.x, cA1.y, cA1.z, cA1.w};
        float xB[8] = {cB0.x, cB0.y, cB0.z, cB0.w, cB1.x, cB1.y, cB1.z, cB1.w};
#pragma unroll
        for (int i = 0; i < 8; i++) {
            unsigned long long xa = pack2(xA[i], xA[i]);
            unsigned long long xb = pack2(xB[i], xB[i]);
#pragma unroll
            for (int p = 0; p < 10; p++) {
                fma2(accA[p], xa, w2[i * 10 + p]);
                fma2(accB[p], xb, w2[i * 10 + p]);
            }
        }

        {
            ulonglong2* dA = (ulonglong2*)(redA + lane * 20);
            ulonglong2* dB = (ulonglong2*)(redB + lane * 20);
#pragma unroll
            for (int q = 0; q < 5; q++) {
                dA[q] = make_ulonglong2(accA[2 * q], accA[2 * q + 1]);
                dB[q] = make_ulonglong2(accB[2 * q], accB[2 * q + 1]);
            }
        }
        __syncwarp();

        if (lane < 20) {
            float sA0 = 0.f, sA1 = 0.f, sB0 = 0.f, sB1 = 0.f;
#pragma unroll
            for (int l = 0; l < 32; l += 2) {
                sA0 += redA[(l + 0) * 20 + lane];
                sA1 += redA[(l + 1) * 20 + lane];
                sB0 += redB[(l + 0) * 20 + lane];
                sB1 += redB[(l + 1) * 20 + lane];
            }
            float vA = sA0 + sA1 + blane;
            float vB = sB0 + sB1 + blane;

            // compact 16-float row layout
            int idx;
            if (lane < 5) {
                idx = lane;                                  // k0..k4 -> 0..4
            } else if (lane < 10) {
                int s = lane - 5;                            // q_s
                idx = (s < 4) ? (8 + 2 * s) : 5;
            } else if (lane < 15) {
                int s = lane - 10;                           // v_s
                idx = (s < 4) ? (9 + 2 * s) : 6;
            } else {
                ag[(size_t)n * 8 + (lane - 15)] = vA;        // skip term
                if (hb) ag[(size_t)(n + 1) * 8 + (lane - 15)] = vB;
                idx = -1;
            }
            if (idx >= 0) {
                kq[(size_t)n * 16 + idx] = vA;
                if (hb) kq[(size_t)(n + 1) * 16 + idx] = vB;
            }
        }
        __syncwarp();
        n = nn;
    }
}

// ---------------------------------------------------------------------------
// K1b: edge-attr GEMV, standalone at full occupancy (pure eatt stream).
// 4 lanes/edge, 2 edges/iter, cross-iteration prefetch.
__global__ __launch_bounds__(256) void edge_gemv(
    const float* __restrict__ eatt,
    const float* __restrict__ We1, const float* __restrict__ be1,
    const float* __restrict__ We2, const float* __restrict__ be2,
    int E)
{
    int tid = threadIdx.x;
    int c   = tid & 3;
    int grp = (tid >> 2) & 7;
    int wid = tid >> 5;

    unsigned long long w01[8], w23[8], w4e[8];
#pragma unroll
    for (int i = 0; i < 8; i++) {
        int col = c * 8 + i;
        w01[i] = pack2(__ldg(&We1[col * 5 + 0]), __ldg(&We1[col * 5 + 1]));
        w23[i] = pack2(__ldg(&We1[col * 5 + 2]), __ldg(&We1[col * 5 + 3]));
        w4e[i] = pack2(__ldg(&We1[col * 5 + 4]), __ldg(&We2[col]));
    }
    float b0 = __ldg(&be1[0]), b1 = __ldg(&be1[1]), b2 = __ldg(&be1[2]);
    float b3 = __ldg(&be1[3]), b4 = __ldg(&be1[4]);
    float bec2 = __ldg(be2);

    const float4* ea4 = (const float4*)eatt;
    const int WTOT  = gridDim.x * 8;
    const int estep = 2 * WTOT * 8;
    int wg = blockIdx.x * 8 + wid;

    int ew = wg * 8;
    float4 a0, a1, q0, q1;
    if (ew < E) {
        int eA = ew + grp;
        int eB = ew + WTOT * 8 + grp;
        size_t iA = (size_t)(eA < E ? eA : 0);
        size_t iB = (size_t)(eB < E ? eB : 0);
        a0 = __ldg(&ea4[iA * 8 + c * 2]);
        a1 = __ldg(&ea4[iA * 8 + c * 2 + 1]);
        q0 = __ldg(&ea4[iB * 8 + c * 2]);
        q1 = __ldg(&ea4[iB * 8 + c * 2 + 1]);
    }

    while (ew < E) {
        int ewn = ew + estep;
        float4 na0, na1, nq0, nq1;
        if (ewn < E) {
            int eA = ewn + grp;
            int eB = ewn + WTOT * 8 + grp;
            size_t iA = (size_t)(eA < E ? eA : 0);
            size_t iB = (size_t)(eB < E ? eB : 0);
            na0 = __ldg(&ea4[iA * 8 + c * 2]);
            na1 = __ldg(&ea4[iA * 8 + c * 2 + 1]);
            nq0 = __ldg(&ea4[iB * 8 + c * 2]);
            nq1 = __ldg(&ea4[iB * 8 + c * 2 + 1]);
        }

        int eA = ew + grp;
        int eB = ew + WTOT * 8 + grp;
        bool vA = eA < E, vB = eB < E;

        unsigned long long pA01 = 0ull, pA23 = 0ull, pA4e = 0ull;
        unsigned long long pB01 = 0ull, pB23 = 0ull, pB4e = 0ull;
        float xsA[8] = {a0.x, a0.y, a0.z, a0.w, a1.x, a1.y, a1.z, a1.w};
        float xsB[8] = {q0.x, q0.y, q0.z, q0.w, q1.x, q1.y, q1.z, q1.w};
#pragma unroll
        for (int i = 0; i < 8; i++) {
            unsigned long long xa = pack2(xsA[i], xsA[i]);
            unsigned long long xb = pack2(xsB[i], xsB[i]);
            fma2(pA01, xa, w01[i]); fma2(pA23, xa, w23[i]); fma2(pA4e, xa, w4e[i]);
            fma2(pB01, xb, w01[i]); fma2(pB23, xb, w23[i]); fma2(pB4e, xb, w4e[i]);
        }
#pragma unroll
        for (int off = 2; off > 0; off >>= 1) {
            pA01 = add2(pA01, __shfl_xor_sync(0xffffffffu, pA01, off, 4));
            pA23 = add2(pA23, __shfl_xor_sync(0xffffffffu, pA23, off, 4));
            pA4e = add2(pA4e, __shfl_xor_sync(0xffffffffu, pA4e, off, 4));
            pB01 = add2(pB01, __shfl_xor_sync(0xffffffffu, pB01, off, 4));
            pB23 = add2(pB23, __shfl_xor_sync(0xffffffffu, pB23, off, 4));
            pB4e = add2(pB4e, __shfl_xor_sync(0xffffffffu, pB4e, off, 4));
        }
        float eA0, eA1, eA2, eA3, eA4, eAc2;
        unpack2(pA01, eA0, eA1); unpack2(pA23, eA2, eA3); unpack2(pA4e, eA4, eAc2);
        float eB0, eB1, eB2, eB3, eB4, eBc2;
        unpack2(pB01, eB0, eB1); unpack2(pB23, eB2, eB3); unpack2(pB4e, eB4, eBc2);

        if (vA) {
            if (c == 0)      g_e1a[eA] = make_float4(eA0 + b0, eA1 + b1, eA2 + b2, eA3 + b3);
            else if (c == 1) g_e1b[eA] = eA4 + b4;
            else if (c == 2) g_e2[eA]  = eAc2 + bec2;
        }
        if (vB) {
            if (c == 0)      g_e1a[eB] = make_float4(eB0 + b0, eB1 + b1, eB2 + b2, eB3 + b3);
            else if (c == 1) g_e1b[eB] = eB4 + b4;
            else if (c == 2) g_e2[eB]  = eBc2 + bec2;
        }

        a0 = na0; a1 = na1; q0 = nq0; q1 = nq1;
        ew = ewn;
    }
}

// ---------------------------------------------------------------------------
// K2: conv1 gate + aggregate. One thread per edge, 2 independent edges/thread,
// full-occupancy grid. Node rows are 64B.
__global__ __launch_bounds__(256) void gate_agg(const int* __restrict__ ei, int E)
{
    int half = ((E + 511) / 512) * 256;
    int gid  = blockIdx.x * 256 + threadIdx.x;
    if (gid >= half) return;

    float* agf = (float*)g_aggv;

    int eA = gid;
    int eB = gid + half;
    bool vB = eB < E;
    size_t iB = (size_t)(vB ? eB : 0);

    int sA = __ldg(&ei[eA]), dA = __ldg(&ei[E + eA]);
    int sB = __ldg(&ei[iB]), dB = __ldg(&ei[E + iB]);

    float4 eA03 = __ldg(&g_e1a[eA]);
    float  eA4  = __ldg(&g_e1b[eA]);
    float4 eB03 = __ldg(&g_e1a[iB]);
    float  eB4  = __ldg(&g_e1b[iB]);

    float4 kA03 = __ldg(&g_kqv1[(size_t)dA * 4]);
    float4 kA4  = __ldg(&g_kqv1[(size_t)dA * 4 + 1]);
    float4 sA4  = __ldg(&g_kqv1[(size_t)sA * 4 + 1]);
    float4 qA01 = __ldg(&g_kqv1[(size_t)sA * 4 + 2]);
    float4 qA23 = __ldg(&g_kqv1[(size_t)sA * 4 + 3]);

    float4 kB03 = __ldg(&g_kqv1[(size_t)dB * 4]);
    float4 kB4  = __ldg(&g_kqv1[(size_t)dB * 4 + 1]);
    float4 sB4  = __ldg(&g_kqv1[(size_t)sB * 4 + 1]);
    float4 qB01 = __ldg(&g_kqv1[(size_t)sB * 4 + 2]);
    float4 qB23 = __ldg(&g_kqv1[(size_t)sB * 4 + 3]);

    {
        float m0 = fast_sigmoid(kA03.x + qA01.x + 2.f * eA03.x) * (qA01.y + eA03.x);
        float m1 = fast_sigmoid(kA03.y + qA01.z + 2.f * eA03.y) * (qA01.w + eA03.y);
        float m2 = fast_sigmoid(kA03.z + qA23.x + 2.f * eA03.z) * (qA23.y + eA03.z);
        float m3 = fast_sigmoid(kA03.w + qA23.z + 2.f * eA03.w) * (qA23.w + eA03.w);
        float m4 = fast_sigmoid(kA4.x  + sA4.y  + 2.f * eA4)    * (sA4.z  + eA4);
        atomicAdd(&g_aggv[(size_t)dA * 2], make_float4(m0, m1, m2, m3));
        atomicAdd(&agf[(size_t)dA * 8 + 4], m4);
    }
    if (vB) {
        float m0 = fast_sigmoid(kB03.x + qB01.x + 2.f * eB03.x) * (qB01.y + eB03.x);
        float m1 = fast_sigmoid(kB03.y + qB01.z + 2.f * eB03.y) * (qB01.w + eB03.y);
        float m2 = fast_sigmoid(kB03.z + qB23.x + 2.f * eB03.z) * (qB23.y + eB03.z);
        float m3 = fast_sigmoid(kB03.w + qB23.z + 2.f * eB03.w) * (qB23.w + eB03.w);
        float m4 = fast_sigmoid(kB4.x  + sB4.y  + 2.f * eB4)    * (sB4.z  + eB4);
        atomicAdd(&g_aggv[(size_t)dB * 2], make_float4(m0, m1, m2, m3));
        atomicAdd(&agf[(size_t)dB * 8 + 4], m4);
    }
}

// ---------------------------------------------------------------------------
__device__ __forceinline__ void grid_barrier(unsigned target)
{
    __syncthreads();
    if (threadIdx.x == 0) {
        __threadfence();
        atomicAdd(&g_bar, 1u);
        while (*(volatile unsigned*)&g_bar < target) { }
        __threadfence();
    }
    __syncthreads();
}

// ---------------------------------------------------------------------------
// K3: fused tail — gnorm stats -> A,B -> norm+relu+proj2 -> edge pass2 ->
// final sigmoid, separated by grid barriers.
__global__ __launch_bounds__(NT3) void fused_tail(
    const int* __restrict__ batch, const int* __restrict__ ei,
    const float* __restrict__ gw, const float* __restrict__ gb,
    const float* __restrict__ gms,
    const float* __restrict__ Wk2, const float* __restrict__ bk2,
    const float* __restrict__ Wq2, const float* __restrict__ bq2,
    const float* __restrict__ Wv2, const float* __restrict__ bv2,
    const float* __restrict__ Ws2, const float* __restrict__ b2,
    float* __restrict__ out, int N, int E)
{
    __shared__ float ssum[NGRP * 5], ssq[NGRP * 5], scnt[NGRP];
    __shared__ float sA[NGRP * 5], sB[NGRP * 5];

    int tid  = threadIdx.x;
    int lane = tid & 31;
    const float* agf = (const float*)g_aggv;

    // ---- phase 1: group statistics -----------------------------------------
    for (int i = tid; i < NGRP * 5; i += NT3) { ssum[i] = 0.f; ssq[i] = 0.f; }
    if (tid < NGRP) scnt[tid] = 0.f;
    __syncthreads();

#pragma unroll
    for (int it = 0; it < 2; it++) {
        int n = blockIdx.x * NT3 + tid + it * GS3;
        bool valid = n < N;
        unsigned act = __ballot_sync(0xffffffffu, valid);
        if (act == 0) continue;

        int g  = valid ? __ldg(&batch[n]) : 0;
        int g0 = __shfl_sync(0xffffffffu, g, 0);
        bool uni = __all_sync(0xffffffffu, valid && (g == g0));

        float v[5];
        float4 v4 = valid ? __ldg((const float4*)(agf + (size_t)n * 8))
                          : make_float4(0.f, 0.f, 0.f, 0.f);
        float  v5 = valid ? __ldg(agf + (size_t)n * 8 + 4) : 0.f;
        v[0] = v4.x; v[1] = v4.y; v[2] = v4.z; v[3] = v4.w; v[4] = v5;

        if (uni) {
#pragma unroll
            for (int h = 0; h < 5; h++) {
                float sv = v[h], sq = v[h] * v[h];
#pragma unroll
                for (int off = 16; off > 0; off >>= 1) {
                    sv += __shfl_xor_sync(0xffffffffu, sv, off);
                    sq += __shfl_xor_sync(0xffffffffu, sq, off);
                }
                if (lane == 0) {
                    atomicAdd(&ssum[g0 * 5 + h], sv);
                    atomicAdd(&ssq[g0 * 5 + h], sq);
                }
            }
            if (lane == 0) atomicAdd(&scnt[g0], 32.f);
        } else if (valid) {
#pragma unroll
            for (int h = 0; h < 5; h++) {
                atomicAdd(&ssum[g * 5 + h], v[h]);
                atomicAdd(&ssq[g * 5 + h], v[h] * v[h]);
            }
            atomicAdd(&scnt[g], 1.f);
        }
    }
    __syncthreads();
    for (int i = tid; i < NGRP * 5; i += NT3) {
        atomicAdd(&g_gsum[i], ssum[i]);
        atomicAdd(&g_gsq[i],  ssq[i]);
    }
    if (tid < NGRP) atomicAdd(&g_gcnt[tid], scnt[tid]);

    grid_barrier(1u * NB3);

    // ---- phase 2: per-group affine ------------------------------------------
    if (tid < NGRP * 5) {
        int g = tid / 5, h = tid % 5;
        float cnt  = fmaxf(__ldcg(&g_gcnt[g]), 1.f);
        float mean = __ldcg(&g_gsum[tid]) / cnt;
        float ex2  = __ldcg(&g_gsq[tid])  / cnt;
        float ms   = __ldg(&gms[h]);
        float d    = mean * ms;
        float var  = ex2 - 2.f * d * mean + d * d;
        float inv  = rsqrtf(var + 1e-5f);
        float wv   = __ldg(&gw[h]);
        sA[tid] = wv * inv;
        sB[tid] = __ldg(&gb[h]) - wv * inv * d;
    }
    __syncthreads();

    // ---- phase 3: norm + relu + conv2 node projections ----------------------
    float k2b = __ldg(bk2), q2b = __ldg(bq2), v2b = __ldg(bv2), s2b = __ldg(b2);
    float wk[5], wq[5], wv5[5], wsk[5];
#pragma unroll
    for (int h = 0; h < 5; h++) {
        wk[h]  = __ldg(&Wk2[h]); wq[h]  = __ldg(&Wq2[h]);
        wv5[h] = __ldg(&Wv2[h]); wsk[h] = __ldg(&Ws2[h]);
    }
#pragma unroll
    for (int it = 0; it < 2; it++) {
        int n = blockIdx.x * NT3 + tid + it * GS3;
        if (n < N) {
            int g = __ldg(&batch[n]);
            float4 a4 = __ldg((const float4*)(agf + (size_t)n * 8));
            float  a5 = __ldg(agf + (size_t)n * 8 + 4);
            float av[5] = {a4.x, a4.y, a4.z, a4.w, a5};
            float k2 = k2b, q2 = q2b, v2 = v2b, s2 = s2b;
#pragma unroll
            for (int h = 0; h < 5; h++) {
                float hv = fmaxf(fmaf(sA[g * 5 + h], av[h], sB[g * 5 + h]), 0.f);
                k2 = fmaf(hv, wk[h],  k2);
                q2 = fmaf(hv, wq[h],  q2);
                v2 = fmaf(hv, wv5[h], v2);
                s2 = fmaf(hv, wsk[h], s2);
            }
            g_kqv2[n] = make_float4(k2, q2, v2, 0.f);
            out[n]    = s2;
        }
    }

    grid_barrier(2u * NB3);

    // ---- phase 4: conv2 edge pass (2-wide for MLP) ---------------------------
    {
        int base = blockIdx.x * NT3 + tid;
        for (int e = base; e < E; e += 2 * GS3) {
            int eb = e + GS3;
            bool hb = eb < E;
            int sa = __ldg(&ei[e]),  da = __ldg(&ei[E + e]);
            int sb = hb ? __ldg(&ei[eb]) : 0;
            int db = hb ? __ldg(&ei[E + eb]) : 0;
            float eva = __ldg(&g_e2[e]);
            float evb = hb ? __ldg(&g_e2[eb]) : 0.f;
            float4 da4 = __ldcg(&g_kqv2[da]);
            float4 sa4 = __ldcg(&g_kqv2[sa]);
            float4 db4 = hb ? __ldcg(&g_kqv2[db]) : make_float4(0, 0, 0, 0);
            float4 sb4 = hb ? __ldcg(&g_kqv2[sb]) : make_float4(0, 0, 0, 0);
            float ga = fast_sigmoid(da4.x + sa4.y + 2.f * eva);
            atomicAdd(&out[da], ga * (sa4.z + eva));
            if (hb) {
                float gbv = fast_sigmoid(db4.x + sb4.y + 2.f * evb);
                atomicAdd(&out[db], gbv * (sb4.z + evb));
            }
        }
    }

    grid_barrier(3u * NB3);

    // ---- phase 5: final sigmoid ----------------------------------------------
#pragma unroll
    for (int it = 0; it < 2; it++) {
        int n = blockIdx.x * NT3 + tid + it * GS3;
        if (n < N) out[n] = fast_sigmoid(__ldcg(&out[n]));
    }
}

// ---------------------------------------------------------------------------
extern "C" void kernel_launch(void* const* d_in, const int* in_sizes, int n_in,
                              void* d_out, int out_size)
{
    const float* x     = (const float*)d_in[0];
    const float* eatt  = (const float*)d_in[1];
    const int*   ei    = (const int*)d_in[2];
    const int*   batch = (const int*)d_in[3];
    const float* Wk1 = (const float*)d_in[4];
    const float* bk1 = (const float*)d_in[5];
    const float* Wq1 = (const float*)d_in[6];
    const float* bq1 = (const float*)d_in[7];
    const float* Wv1 = (const float*)d_in[8];
    const float* bv1 = (const float*)d_in[9];
    const float* We1 = (const float*)d_in[10];
    const float* be1 = (const float*)d_in[11];
    const float* Ws1 = (const float*)d_in[12];
    const float* b1  = (const float*)d_in[13];
    const float* gw  = (const float*)d_in[14];
    const float* gb  = (const float*)d_in[15];
    const float* gms = (const float*)d_in[16];
    const float* Wk2 = (const float*)d_in[17];
    const float* bk2 = (const float*)d_in[18];
    const float* Wq2 = (const float*)d_in[19];
    const float* bq2 = (const float*)d_in[20];
    const float* Wv2 = (const float*)d_in[21];
    const float* bv2 = (const float*)d_in[22];
    const float* We2 = (const float*)d_in[23];
    const float* be2 = (const float*)d_in[24];
    const float* Ws2 = (const float*)d_in[25];
    const float* b2  = (const float*)d_in[26];
    float* out = (float*)d_out;

    int N = in_sizes[3];
    int E = in_sizes[2] / 2;
    if (N > NMAX) N = NMAX;
    if (E > EMAX) E = EMAX;

    int gb2 = (E + 511) / 512;   // gate_agg blocks (2 edges/thread)

    node_proj1<<<148, 256>>>(x, Wk1, bk1, Wq1, bq1, Wv1, bv1, Ws1, b1, N);
    edge_gemv<<<1184, 256>>>(eatt, We1, be1, We2, be2, E);
    gate_agg<<<gb2, 256>>>(ei, E);
    fused_tail<<<NB3, NT3>>>(batch, ei, gw, gb, gms,
                             Wk2, bk2, Wq2, bq2, Wv2, bv2, Ws2, b2,
                             out, N, E);
}

// round 15
// speedup vs baseline: 1.2049x; 1.0202x over previous
#include <cuda_runtime.h>

// ---------------- problem constants ----------------------------------------
#define NMAX 100000
#define EMAX 1600000
#define NGRP 64

// ---------------- scratch (__device__ globals) -----------------------------
// per node 16 floats (64B): [k0..k3][k4,q4,v4,_][q0,v0,q1,v1][q2,v2,q3,v3]
__device__ float4   g_kqv1[NMAX * 4];
__device__ float4   g_aggv[NMAX * 2];    // per node 8 f: conv1 agg in [0..5)
__device__ float4   g_e1a[EMAX];         // per-edge conv1 proj h0..h3 (+bias)
__device__ float    g_e1b[EMAX];         // per-edge conv1 proj h4 (+bias)
__device__ float    g_e2[EMAX];          // per-edge conv2 edge projection (+bias)
__device__ float4   g_kqv2[NMAX];        // conv2 node proj (k2,q2,v2,_)
__device__ float    g_gsum[NGRP * 5];
__device__ float    g_gsq[NGRP * 5];
__device__ float    g_gcnt[NGRP];

// sigmoid via MUFU.TANH: 1 MUFU instead of 2. rel_err ~1e-6, well under 1e-3.
__device__ __forceinline__ float fast_sigmoid(float z) {
    float t;
    asm("tanh.approx.f32 %0, %1;" : "=f"(t) : "f"(z * 0.5f));
    return fmaf(t, 0.5f, 0.5f);
}

// ---- packed f32x2 helpers (ptxas won't emit FFMA2/FADD2 from C++) ---------
__device__ __forceinline__ unsigned long long pack2(float a, float b) {
    unsigned long long r;
    asm("mov.b64 %0, {%1, %2};" : "=l"(r) : "f"(a), "f"(b));
    return r;
}
__device__ __forceinline__ void unpack2(unsigned long long v, float& a, float& b) {
    asm("mov.b64 {%0, %1}, %2;" : "=f"(a), "=f"(b) : "l"(v));
}
__device__ __forceinline__ void fma2(unsigned long long& d,
                                     unsigned long long a, unsigned long long b) {
    asm("fma.rn.f32x2 %0, %1, %2, %0;" : "+l"(d) : "l"(a), "l"(b));
}
__device__ __forceinline__ unsigned long long add2(unsigned long long a,
                                                   unsigned long long b) {
    unsigned long long r;
    asm("add.rn.f32x2 %0, %1, %2;" : "=l"(r) : "l"(a), "l"(b));
    return r;
}

// ---------------------------------------------------------------------------
// K1a: conv1 node GEMM (R5 champion: 1 block/SM, warp-per-node, 80 u64 weight
// regs, two nodes/iter for ILP, smem transpose reduce).
__global__ __launch_bounds__(256, 1) void node_proj1(
    const float* __restrict__ x,
    const float* __restrict__ Wk, const float* __restrict__ bk,
    const float* __restrict__ Wq, const float* __restrict__ bq,
    const float* __restrict__ Wv, const float* __restrict__ bv,
    const float* __restrict__ Ws, const float* __restrict__ bs,
    int N)
{
    __shared__ __align__(16) float sbuf[10240];   // 40KB, dual-purpose

    int tid  = threadIdx.x;
    int lane = tid & 31;
    int wid  = tid >> 5;

    if (blockIdx.x == 0) {                        // fold zero_stats
        for (int i = tid; i < NGRP * 5; i += 256) { g_gsum[i] = 0.f; g_gsq[i] = 0.f; }
        if (tid < NGRP) g_gcnt[tid] = 0.f;
    }

    for (int i = tid; i < 256 * 20; i += 256) {
        int c = i / 20, h = i % 20;
        float v;
        if (h < 5)       v = Wk[c * 5 + h];
        else if (h < 10) v = Wq[c * 5 + h - 5];
        else if (h < 15) v = Wv[c * 5 + h - 10];
        else             v = Ws[c * 5 + h - 15];
        sbuf[c * 21 + h] = v;
    }
    __syncthreads();

    unsigned long long w2[80];
#pragma unroll
    for (int i = 0; i < 8; i++) {
        int c = lane * 8 + i;
#pragma unroll
        for (int p = 0; p < 10; p++)
            w2[i * 10 + p] = pack2(sbuf[c * 21 + 2 * p], sbuf[c * 21 + 2 * p + 1]);
    }
    __syncthreads();

    float blane = 0.f;
    if (lane < 5)       blane = __ldg(&bk[lane]);
    else if (lane < 10) blane = __ldg(&bq[lane - 5]);
    else if (lane < 15) blane = __ldg(&bv[lane - 10]);
    else if (lane < 20) blane = __ldg(&bs[lane - 15]);

    float* redA = &sbuf[wid * 1280];
    float* redB = redA + 640;
    float* kq   = (float*)g_kqv1;
    float* ag   = (float*)g_aggv;

    int warp = blockIdx.x * 8 + wid;
    int step = gridDim.x * 8 * 2;

    int n = warp * 2;
    float4 a0A, a1A, a0B, a1B;
    if (n < N) {
        const float4* xr = (const float4*)(x + (size_t)n * 256 + lane * 8);
        a0A = __ldg(xr); a1A = __ldg(xr + 1);
    }
    if (n + 1 < N) {
        const float4* xr = (const float4*)(x + (size_t)(n + 1) * 256 + lane * 8);
        a0B = __ldg(xr); a1B = __ldg(xr + 1);
    }

    while (n < N) {
        float4 cA0 = a0A, cA1 = a1A, cB0 = a0B, cB1 = a1B;
        bool hb = (n + 1) < N;
        int nn = n + step;
        if (nn < N) {
            const float4* xr = (const float4*)(x + (size_t)nn * 256 + lane * 8);
            a0A = __ldg(xr); a1A = __ldg(xr + 1);
        }
        if (nn + 1 < N) {
            const float4* xr = (const float4*)(x + (size_t)(nn + 1) * 256 + lane * 8);
            a0B = __ldg(xr); a1B = __ldg(xr + 1);
        }

        unsigned long long accA[10], accB[10];
#pragma unroll
        for (int p = 0; p < 10; p++) { accA[p] = 0ull; accB[p] = 0ull; }

        float xA[8] = {cA0.x, cA0.y, cA0.z, cA0.w, cA1.x, cA1.y, cA1.z, cA1.w};
        float xB[8] = {cB0.x, cB0.y, cB0.z, cB0.w, cB1.x, cB1.y, cB1.z, cB1.w};
#pragma unroll
        for (int i = 0; i < 8; i++) {
            unsigned long long xa = pack2(xA[i], xA[i]);
            unsigned long long xb = pack2(xB[i], xB[i]);
#pragma unroll
            for (int p = 0; p < 10; p++) {
                fma2(accA[p], xa, w2[i * 10 + p]);
                fma2(accB[p], xb, w2[i * 10 + p]);
            }
        }

        {
            ulonglong2* dA = (ulonglong2*)(redA + lane * 20);
            ulonglong2* dB = (ulonglong2*)(redB + lane * 20);
#pragma unroll
            for (int q = 0; q < 5; q++) {
                dA[q] = make_ulonglong2(accA[2 * q], accA[2 * q + 1]);
                dB[q] = make_ulonglong2(accB[2 * q], accB[2 * q + 1]);
            }
        }
        __syncwarp();

        if (lane < 20) {
            float sA0 = 0.f, sA1 = 0.f, sB0 = 0.f, sB1 = 0.f;
#pragma unroll
            for (int l = 0; l < 32; l += 2) {
                sA0 += redA[(l + 0) * 20 + lane];
                sA1 += redA[(l + 1) * 20 + lane];
                sB0 += redB[(l + 0) * 20 + lane];
                sB1 += redB[(l + 1) * 20 + lane];
            }
            float vA = sA0 + sA1 + blane;
            float vB = sB0 + sB1 + blane;

            int idx;
            if (lane < 5) {
                idx = lane;
            } else if (lane < 10) {
                int s = lane - 5;
                idx = (s < 4) ? (8 + 2 * s) : 5;
            } else if (lane < 15) {
                int s = lane - 10;
                idx = (s < 4) ? (9 + 2 * s) : 6;
            } else {
                ag[(size_t)n * 8 + (lane - 15)] = vA;
                if (hb) ag[(size_t)(n + 1) * 8 + (lane - 15)] = vB;
                idx = -1;
            }
            if (idx >= 0) {
                kq[(size_t)n * 16 + idx] = vA;
                if (hb) kq[(size_t)(n + 1) * 16 + idx] = vB;
            }
        }
        __syncwarp();
        n = nn;
    }
}

// ---------------------------------------------------------------------------
// K1b: edge-attr GEMV, full occupancy (pure eatt stream).
__global__ __launch_bounds__(256) void edge_gemv(
    const float* __restrict__ eatt,
    const float* __restrict__ We1, const float* __restrict__ be1,
    const float* __restrict__ We2, const float* __restrict__ be2,
    int E)
{
    int tid = threadIdx.x;
    int c   = tid & 3;
    int grp = (tid >> 2) & 7;
    int wid = tid >> 5;

    unsigned long long w01[8], w23[8], w4e[8];
#pragma unroll
    for (int i = 0; i < 8; i++) {
        int col = c * 8 + i;
        w01[i] = pack2(__ldg(&We1[col * 5 + 0]), __ldg(&We1[col * 5 + 1]));
        w23[i] = pack2(__ldg(&We1[col * 5 + 2]), __ldg(&We1[col * 5 + 3]));
        w4e[i] = pack2(__ldg(&We1[col * 5 + 4]), __ldg(&We2[col]));
    }
    float b0 = __ldg(&be1[0]), b1 = __ldg(&be1[1]), b2 = __ldg(&be1[2]);
    float b3 = __ldg(&be1[3]), b4 = __ldg(&be1[4]);
    float bec2 = __ldg(be2);

    const float4* ea4 = (const float4*)eatt;
    const int WTOT  = gridDim.x * 8;
    const int estep = 2 * WTOT * 8;
    int wg = blockIdx.x * 8 + wid;

    int ew = wg * 8;
    float4 a0, a1, q0, q1;
    if (ew < E) {
        int eA = ew + grp;
        int eB = ew + WTOT * 8 + grp;
        size_t iA = (size_t)(eA < E ? eA : 0);
        size_t iB = (size_t)(eB < E ? eB : 0);
        a0 = __ldg(&ea4[iA * 8 + c * 2]);
        a1 = __ldg(&ea4[iA * 8 + c * 2 + 1]);
        q0 = __ldg(&ea4[iB * 8 + c * 2]);
        q1 = __ldg(&ea4[iB * 8 + c * 2 + 1]);
    }

    while (ew < E) {
        int ewn = ew + estep;
        float4 na0, na1, nq0, nq1;
        if (ewn < E) {
            int eA = ewn + grp;
            int eB = ewn + WTOT * 8 + grp;
            size_t iA = (size_t)(eA < E ? eA : 0);
            size_t iB = (size_t)(eB < E ? eB : 0);
            na0 = __ldg(&ea4[iA * 8 + c * 2]);
            na1 = __ldg(&ea4[iA * 8 + c * 2 + 1]);
            nq0 = __ldg(&ea4[iB * 8 + c * 2]);
            nq1 = __ldg(&ea4[iB * 8 + c * 2 + 1]);
        }

        int eA = ew + grp;
        int eB = ew + WTOT * 8 + grp;
        bool vA = eA < E, vB = eB < E;

        unsigned long long pA01 = 0ull, pA23 = 0ull, pA4e = 0ull;
        unsigned long long pB01 = 0ull, pB23 = 0ull, pB4e = 0ull;
        float xsA[8] = {a0.x, a0.y, a0.z, a0.w, a1.x, a1.y, a1.z, a1.w};
        float xsB[8] = {q0.x, q0.y, q0.z, q0.w, q1.x, q1.y, q1.z, q1.w};
#pragma unroll
        for (int i = 0; i < 8; i++) {
            unsigned long long xa = pack2(xsA[i], xsA[i]);
            unsigned long long xb = pack2(xsB[i], xsB[i]);
            fma2(pA01, xa, w01[i]); fma2(pA23, xa, w23[i]); fma2(pA4e, xa, w4e[i]);
            fma2(pB01, xb, w01[i]); fma2(pB23, xb, w23[i]); fma2(pB4e, xb, w4e[i]);
        }
#pragma unroll
        for (int off = 2; off > 0; off >>= 1) {
            pA01 = add2(pA01, __shfl_xor_sync(0xffffffffu, pA01, off, 4));
            pA23 = add2(pA23, __shfl_xor_sync(0xffffffffu, pA23, off, 4));
            pA4e = add2(pA4e, __shfl_xor_sync(0xffffffffu, pA4e, off, 4));
            pB01 = add2(pB01, __shfl_xor_sync(0xffffffffu, pB01, off, 4));
            pB23 = add2(pB23, __shfl_xor_sync(0xffffffffu, pB23, off, 4));
            pB4e = add2(pB4e, __shfl_xor_sync(0xffffffffu, pB4e, off, 4));
        }
        float eA0, eA1, eA2, eA3, eA4, eAc2;
        unpack2(pA01, eA0, eA1); unpack2(pA23, eA2, eA3); unpack2(pA4e, eA4, eAc2);
        float eB0, eB1, eB2, eB3, eB4, eBc2;
        unpack2(pB01, eB0, eB1); unpack2(pB23, eB2, eB3); unpack2(pB4e, eB4, eBc2);

        if (vA) {
            if (c == 0)      g_e1a[eA] = make_float4(eA0 + b0, eA1 + b1, eA2 + b2, eA3 + b3);
            else if (c == 1) g_e1b[eA] = eA4 + b4;
            else if (c == 2) g_e2[eA]  = eAc2 + bec2;
        }
        if (vB) {
            if (c == 0)      g_e1a[eB] = make_float4(eB0 + b0, eB1 + b1, eB2 + b2, eB3 + b3);
            else if (c == 1) g_e1b[eB] = eB4 + b4;
            else if (c == 2) g_e2[eB]  = eBc2 + bec2;
        }

        a0 = na0; a1 = na1; q0 = nq0; q1 = nq1;
        ew = ewn;
    }
}

// ---------------------------------------------------------------------------
// K2: conv1 gate + aggregate. One thread per edge, 2 edges/thread, full grid.
__global__ __launch_bounds__(256) void gate_agg(const int* __restrict__ ei, int E)
{
    int half = ((E + 511) / 512) * 256;
    int gid  = blockIdx.x * 256 + threadIdx.x;
    if (gid >= half) return;

    float* agf = (float*)g_aggv;

    int eA = gid;
    int eB = gid + half;
    bool vB = eB < E;
    size_t iB = (size_t)(vB ? eB : 0);

    int sA = __ldg(&ei[eA]), dA = __ldg(&ei[E + eA]);
    int sB = __ldg(&ei[iB]), dB = __ldg(&ei[E + iB]);

    float4 eA03 = __ldg(&g_e1a[eA]);
    float  eA4  = __ldg(&g_e1b[eA]);
    float4 eB03 = __ldg(&g_e1a[iB]);
    float  eB4  = __ldg(&g_e1b[iB]);

    float4 kA03 = __ldg(&g_kqv1[(size_t)dA * 4]);
    float4 kA4  = __ldg(&g_kqv1[(size_t)dA * 4 + 1]);
    float4 sA4  = __ldg(&g_kqv1[(size_t)sA * 4 + 1]);
    float4 qA01 = __ldg(&g_kqv1[(size_t)sA * 4 + 2]);
    float4 qA23 = __ldg(&g_kqv1[(size_t)sA * 4 + 3]);

    float4 kB03 = __ldg(&g_kqv1[(size_t)dB * 4]);
    float4 kB4  = __ldg(&g_kqv1[(size_t)dB * 4 + 1]);
    float4 sB4  = __ldg(&g_kqv1[(size_t)sB * 4 + 1]);
    float4 qB01 = __ldg(&g_kqv1[(size_t)sB * 4 + 2]);
    float4 qB23 = __ldg(&g_kqv1[(size_t)sB * 4 + 3]);

    {
        float m0 = fast_sigmoid(kA03.x + qA01.x + 2.f * eA03.x) * (qA01.y + eA03.x);
        float m1 = fast_sigmoid(kA03.y + qA01.z + 2.f * eA03.y) * (qA01.w + eA03.y);
        float m2 = fast_sigmoid(kA03.z + qA23.x + 2.f * eA03.z) * (qA23.y + eA03.z);
        float m3 = fast_sigmoid(kA03.w + qA23.z + 2.f * eA03.w) * (qA23.w + eA03.w);
        float m4 = fast_sigmoid(kA4.x  + sA4.y  + 2.f * eA4)    * (sA4.z  + eA4);
        atomicAdd(&g_aggv[(size_t)dA * 2], make_float4(m0, m1, m2, m3));
        atomicAdd(&agf[(size_t)dA * 8 + 4], m4);
    }
    if (vB) {
        float m0 = fast_sigmoid(kB03.x + qB01.x + 2.f * eB03.x) * (qB01.y + eB03.x);
        float m1 = fast_sigmoid(kB03.y + qB01.z + 2.f * eB03.y) * (qB01.w + eB03.y);
        float m2 = fast_sigmoid(kB03.z + qB23.x + 2.f * eB03.z) * (qB23.y + eB03.z);
        float m3 = fast_sigmoid(kB03.w + qB23.z + 2.f * eB03.w) * (qB23.w + eB03.w);
        float m4 = fast_sigmoid(kB4.x  + sB4.y  + 2.f * eB4)    * (sB4.z  + eB4);
        atomicAdd(&g_aggv[(size_t)dB * 2], make_float4(m0, m1, m2, m3));
        atomicAdd(&agf[(size_t)dB * 8 + 4], m4);
    }
}

// ---------------------------------------------------------------------------
// K3a: GraphNorm statistics (one element/thread; block-local smem accum).
__global__ __launch_bounds__(256) void gnorm_stats(const int* __restrict__ batch, int N)
{
    __shared__ float ssum[NGRP * 5], ssq[NGRP * 5], scnt[NGRP];
    int tid  = threadIdx.x;
    int lane = tid & 31;
    const float* agf = (const float*)g_aggv;

    for (int i = tid; i < NGRP * 5; i += 256) { ssum[i] = 0.f; ssq[i] = 0.f; }
    if (tid < NGRP) scnt[tid] = 0.f;
    __syncthreads();

    int n = blockIdx.x * 256 + tid;
    bool valid = n < N;
    int g  = valid ? __ldg(&batch[n]) : 0;
    int g0 = __shfl_sync(0xffffffffu, g, 0);
    bool uni = __all_sync(0xffffffffu, valid && (g == g0));

    float v[5];
    float4 v4 = valid ? __ldg((const float4*)(agf + (size_t)n * 8))
                      : make_float4(0.f, 0.f, 0.f, 0.f);
    float  v5 = valid ? __ldg(agf + (size_t)n * 8 + 4) : 0.f;
    v[0] = v4.x; v[1] = v4.y; v[2] = v4.z; v[3] = v4.w; v[4] = v5;

    if (uni) {
#pragma unroll
        for (int h = 0; h < 5; h++) {
            float sv = v[h], sq = v[h] * v[h];
#pragma unroll
            for (int off = 16; off > 0; off >>= 1) {
                sv += __shfl_xor_sync(0xffffffffu, sv, off);
                sq += __shfl_xor_sync(0xffffffffu, sq, off);
            }
            if (lane == 0) {
                atomicAdd(&ssum[g0 * 5 + h], sv);
                atomicAdd(&ssq[g0 * 5 + h], sq);
            }
        }
        if (lane == 0) atomicAdd(&scnt[g0], 32.f);
    } else if (valid) {
#pragma unroll
        for (int h = 0; h < 5; h++) {
            atomicAdd(&ssum[g * 5 + h], v[h]);
            atomicAdd(&ssq[g * 5 + h], v[h] * v[h]);
        }
        atomicAdd(&scnt[g], 1.f);
    }

    __syncthreads();
    for (int i = tid; i < NGRP * 5; i += 256) {
        if (ssum[i] != 0.f) atomicAdd(&g_gsum[i], ssum[i]);
        if (ssq[i]  != 0.f) atomicAdd(&g_gsq[i],  ssq[i]);
    }
    if (tid < NGRP && scnt[tid] != 0.f) atomicAdd(&g_gcnt[tid], scnt[tid]);
}

// ---------------------------------------------------------------------------
// K3b: norm + relu + conv2 node projections. Each block redundantly builds
// the 320-entry (A,B) affine table in smem (reads are L2-hits), then applies.
__global__ __launch_bounds__(256) void node_proj2(
    const int* __restrict__ batch,
    const float* __restrict__ gw, const float* __restrict__ gb,
    const float* __restrict__ gms,
    const float* __restrict__ Wk2, const float* __restrict__ bk2,
    const float* __restrict__ Wq2, const float* __restrict__ bq2,
    const float* __restrict__ Wv2, const float* __restrict__ bv2,
    const float* __restrict__ Ws2, const float* __restrict__ b2,
    float* __restrict__ out, int N)
{
    __shared__ float sA[NGRP * 5], sB[NGRP * 5];
    int tid = threadIdx.x;
    const float* agf = (const float*)g_aggv;

    for (int t = tid; t < NGRP * 5; t += 256) {
        int g = t / 5, h = t % 5;
        float cnt  = fmaxf(g_gcnt[g], 1.f);
        float mean = g_gsum[t] / cnt;
        float ex2  = g_gsq[t]  / cnt;
        float ms   = __ldg(&gms[h]);
        float d    = mean * ms;
        float var  = ex2 - 2.f * d * mean + d * d;
        float inv  = rsqrtf(var + 1e-5f);
        float wv   = __ldg(&gw[h]);
        sA[t] = wv * inv;
        sB[t] = __ldg(&gb[h]) - wv * inv * d;
    }
    __syncthreads();

    int n = blockIdx.x * 256 + tid;
    if (n >= N) return;

    int g = __ldg(&batch[n]);
    float4 a4 = __ldg((const float4*)(agf + (size_t)n * 8));
    float  a5 = __ldg(agf + (size_t)n * 8 + 4);
    float av[5] = {a4.x, a4.y, a4.z, a4.w, a5};
    float k2 = __ldg(bk2), q2 = __ldg(bq2), v2 = __ldg(bv2), s2 = __ldg(b2);
#pragma unroll
    for (int h = 0; h < 5; h++) {
        float hv = fmaxf(fmaf(sA[g * 5 + h], av[h], sB[g * 5 + h]), 0.f);
        k2 = fmaf(hv, __ldg(&Wk2[h]), k2);
        q2 = fmaf(hv, __ldg(&Wq2[h]), q2);
        v2 = fmaf(hv, __ldg(&Wv2[h]), v2);
        s2 = fmaf(hv, __ldg(&Ws2[h]), s2);
    }
    g_kqv2[n] = make_float4(k2, q2, v2, 0.f);
    out[n]    = s2;
}

// ---------------------------------------------------------------------------
// K3c: conv2 edge pass — full-occupancy grid, 2 edges/thread.
__global__ __launch_bounds__(256) void edge_pass2(const int* __restrict__ ei,
                                                  float* __restrict__ out, int E)
{
    int half = ((E + 511) / 512) * 256;
    int gid  = blockIdx.x * 256 + threadIdx.x;
    if (gid >= half) return;

    int eA = gid;
    int eB = gid + half;
    bool vB = eB < E;
    size_t iB = (size_t)(vB ? eB : 0);

    int sa = __ldg(&ei[eA]), da = __ldg(&ei[E + eA]);
    int sb = __ldg(&ei[iB]), db = __ldg(&ei[E + iB]);
    float eva = __ldg(&g_e2[eA]);
    float evb = __ldg(&g_e2[iB]);
    float4 da4 = __ldg(&g_kqv2[da]);
    float4 sa4 = __ldg(&g_kqv2[sa]);
    float4 db4 = __ldg(&g_kqv2[db]);
    float4 sb4 = __ldg(&g_kqv2[sb]);

    float ga = fast_sigmoid(da4.x + sa4.y + 2.f * eva);
    atomicAdd(&out[da], ga * (sa4.z + eva));
    if (vB) {
        float gbv = fast_sigmoid(db4.x + sb4.y + 2.f * evb);
        atomicAdd(&out[db], gbv * (sb4.z + evb));
    }
}

// ---------------------------------------------------------------------------
__global__ void final_sig(float* __restrict__ out, int N)
{
    int n = blockIdx.x * 256 + threadIdx.x;
    if (n < N) out[n] = fast_sigmoid(out[n]);
}

// ---------------------------------------------------------------------------
extern "C" void kernel_launch(void* const* d_in, const int* in_sizes, int n_in,
                              void* d_out, int out_size)
{
    const float* x     = (const float*)d_in[0];
    const float* eatt  = (const float*)d_in[1];
    const int*   ei    = (const int*)d_in[2];
    const int*   batch = (const int*)d_in[3];
    const float* Wk1 = (const float*)d_in[4];
    const float* bk1 = (const float*)d_in[5];
    const float* Wq1 = (const float*)d_in[6];
    const float* bq1 = (const float*)d_in[7];
    const float* Wv1 = (const float*)d_in[8];
    const float* bv1 = (const float*)d_in[9];
    const float* We1 = (const float*)d_in[10];
    const float* be1 = (const float*)d_in[11];
    const float* Ws1 = (const float*)d_in[12];
    const float* b1  = (const float*)d_in[13];
    const float* gw  = (const float*)d_in[14];
    const float* gb  = (const float*)d_in[15];
    const float* gms = (const float*)d_in[16];
    const float* Wk2 = (const float*)d_in[17];
    const float* bk2 = (const float*)d_in[18];
    const float* Wq2 = (const float*)d_in[19];
    const float* bq2 = (const float*)d_in[20];
    const float* Wv2 = (const float*)d_in[21];
    const float* bv2 = (const float*)d_in[22];
    const float* We2 = (const float*)d_in[23];
    const float* be2 = (const float*)d_in[24];
    const float* Ws2 = (const float*)d_in[25];
    const float* b2  = (const float*)d_in[26];
    float* out = (float*)d_out;

    int N = in_sizes[3];
    int E = in_sizes[2] / 2;
    if (N > NMAX) N = NMAX;
    if (E > EMAX) E = EMAX;

    int nb  = (N + 255) / 256;
    int gb2 = (E + 511) / 512;

    node_proj1<<<148, 256>>>(x, Wk1, bk1, Wq1, bq1, Wv1, bv1, Ws1, b1, N);
    edge_gemv<<<1184, 256>>>(eatt, We1, be1, We2, be2, E);
    gate_agg<<<gb2, 256>>>(ei, E);
    gnorm_stats<<<nb, 256>>>(batch, N);
    node_proj2<<<nb, 256>>>(batch, gw, gb, gms,
                            Wk2, bk2, Wq2, bq2, Wv2, bv2, Ws2, b2, out, N);
    edge_pass2<<<gb2, 256>>>(ei, out, E);
    final_sig<<<nb, 256>>>(out, N);
}

// round 16
// speedup vs baseline: 1.2652x; 1.0501x over previous
#include <cuda_runtime.h>

// ---------------- problem constants ----------------------------------------
#define NMAX 100000
#define EMAX 1600000
#define NGRP 64

// ---------------- scratch (__device__ globals) -----------------------------
// per node 16 floats (64B): [k0..k3][k4,q4,v4,_][q0,v0,q1,v1][q2,v2,q3,v3]
__device__ float4   g_kqv1[NMAX * 4];
__device__ float4   g_aggv[NMAX * 2];    // per node 8 f: conv1 agg in [0..5)
__device__ float4   g_e1a[EMAX];         // per-edge conv1 proj h0..h3 (+bias)
__device__ float    g_e1b[EMAX];         // per-edge conv1 proj h4 (+bias)
__device__ float    g_e2[EMAX];          // per-edge conv2 edge projection (+bias)
__device__ float4   g_kqv2[NMAX];        // conv2 node proj (k2,q2,v2,_)
__device__ float    g_gsum[NGRP * 5];
__device__ float    g_gsq[NGRP * 5];
__device__ float    g_gcnt[NGRP];

// sigmoid via MUFU.TANH: 1 MUFU instead of 2. rel_err ~1e-6, well under 1e-3.
__device__ __forceinline__ float fast_sigmoid(float z) {
    float t;
    asm("tanh.approx.f32 %0, %1;" : "=f"(t) : "f"(z * 0.5f));
    return fmaf(t, 0.5f, 0.5f);
}

// ---- packed f32x2 helpers (ptxas won't emit FFMA2/FADD2 from C++) ---------
__device__ __forceinline__ unsigned long long pack2(float a, float b) {
    unsigned long long r;
    asm("mov.b64 %0, {%1, %2};" : "=l"(r) : "f"(a), "f"(b));
    return r;
}
__device__ __forceinline__ void unpack2(unsigned long long v, float& a, float& b) {
    asm("mov.b64 {%0, %1}, %2;" : "=f"(a), "=f"(b) : "l"(v));
}
__device__ __forceinline__ void fma2(unsigned long long& d,
                                     unsigned long long a, unsigned long long b) {
    asm("fma.rn.f32x2 %0, %1, %2, %0;" : "+l"(d) : "l"(a), "l"(b));
}
__device__ __forceinline__ unsigned long long add2(unsigned long long a,
                                                   unsigned long long b) {
    unsigned long long r;
    asm("add.rn.f32x2 %0, %1, %2;" : "=l"(r) : "l"(a), "l"(b));
    return r;
}

// ---------------------------------------------------------------------------
// K1a: conv1 node GEMM (R5 champion: 1 block/SM, warp-per-node, 80 u64 weight
// regs, two nodes/iter for ILP, smem transpose reduce).
__global__ __launch_bounds__(256, 1) void node_proj1(
    const float* __restrict__ x,
    const float* __restrict__ Wk, const float* __restrict__ bk,
    const float* __restrict__ Wq, const float* __restrict__ bq,
    const float* __restrict__ Wv, const float* __restrict__ bv,
    const float* __restrict__ Ws, const float* __restrict__ bs,
    int N)
{
    __shared__ __align__(16) float sbuf[10240];   // 40KB, dual-purpose

    int tid  = threadIdx.x;
    int lane = tid & 31;
    int wid  = tid >> 5;

    if (blockIdx.x == 0) {                        // fold zero_stats
        for (int i = tid; i < NGRP * 5; i += 256) { g_gsum[i] = 0.f; g_gsq[i] = 0.f; }
        if (tid < NGRP) g_gcnt[tid] = 0.f;
    }

    for (int i = tid; i < 256 * 20; i += 256) {
        int c = i / 20, h = i % 20;
        float v;
        if (h < 5)       v = Wk[c * 5 + h];
        else if (h < 10) v = Wq[c * 5 + h - 5];
        else if (h < 15) v = Wv[c * 5 + h - 10];
        else             v = Ws[c * 5 + h - 15];
        sbuf[c * 21 + h] = v;
    }
    __syncthreads();

    unsigned long long w2[80];
#pragma unroll
    for (int i = 0; i < 8; i++) {
        int c = lane * 8 + i;
#pragma unroll
        for (int p = 0; p < 10; p++)
            w2[i * 10 + p] = pack2(sbuf[c * 21 + 2 * p], sbuf[c * 21 + 2 * p + 1]);
    }
    __syncthreads();

    float blane = 0.f;
    if (lane < 5)       blane = __ldg(&bk[lane]);
    else if (lane < 10) blane = __ldg(&bq[lane - 5]);
    else if (lane < 15) blane = __ldg(&bv[lane - 10]);
    else if (lane < 20) blane = __ldg(&bs[lane - 15]);

    float* redA = &sbuf[wid * 1280];
    float* redB = redA + 640;
    float* kq   = (float*)g_kqv1;
    float* ag   = (float*)g_aggv;

    int warp = blockIdx.x * 8 + wid;
    int step = gridDim.x * 8 * 2;

    int n = warp * 2;
    float4 a0A, a1A, a0B, a1B;
    if (n < N) {
        const float4* xr = (const float4*)(x + (size_t)n * 256 + lane * 8);
        a0A = __ldg(xr); a1A = __ldg(xr + 1);
    }
    if (n + 1 < N) {
        const float4* xr = (const float4*)(x + (size_t)(n + 1) * 256 + lane * 8);
        a0B = __ldg(xr); a1B = __ldg(xr + 1);
    }

    while (n < N) {
        float4 cA0 = a0A, cA1 = a1A, cB0 = a0B, cB1 = a1B;
        bool hb = (n + 1) < N;
        int nn = n + step;
        if (nn < N) {
            const float4* xr = (const float4*)(x + (size_t)nn * 256 + lane * 8);
            a0A = __ldg(xr); a1A = __ldg(xr + 1);
        }
        if (nn + 1 < N) {
            const float4* xr = (const float4*)(x + (size_t)(nn + 1) * 256 + lane * 8);
            a0B = __ldg(xr); a1B = __ldg(xr + 1);
        }

        unsigned long long accA[10], accB[10];
#pragma unroll
        for (int p = 0; p < 10; p++) { accA[p] = 0ull; accB[p] = 0ull; }

        float xA[8] = {cA0.x, cA0.y, cA0.z, cA0.w, cA1.x, cA1.y, cA1.z, cA1.w};
        float xB[8] = {cB0.x, cB0.y, cB0.z, cB0.w, cB1.x, cB1.y, cB1.z, cB1.w};
#pragma unroll
        for (int i = 0; i < 8; i++) {
            unsigned long long xa = pack2(xA[i], xA[i]);
            unsigned long long xb = pack2(xB[i], xB[i]);
#pragma unroll
            for (int p = 0; p < 10; p++) {
                fma2(accA[p], xa, w2[i * 10 + p]);
                fma2(accB[p], xb, w2[i * 10 + p]);
            }
        }

        {
            ulonglong2* dA = (ulonglong2*)(redA + lane * 20);
            ulonglong2* dB = (ulonglong2*)(redB + lane * 20);
#pragma unroll
            for (int q = 0; q < 5; q++) {
                dA[q] = make_ulonglong2(accA[2 * q], accA[2 * q + 1]);
                dB[q] = make_ulonglong2(accB[2 * q], accB[2 * q + 1]);
            }
        }
        __syncwarp();

        if (lane < 20) {
            float sA0 = 0.f, sA1 = 0.f, sB0 = 0.f, sB1 = 0.f;
#pragma unroll
            for (int l = 0; l < 32; l += 2) {
                sA0 += redA[(l + 0) * 20 + lane];
                sA1 += redA[(l + 1) * 20 + lane];
                sB0 += redB[(l + 0) * 20 + lane];
                sB1 += redB[(l + 1) * 20 + lane];
            }
            float vA = sA0 + sA1 + blane;
            float vB = sB0 + sB1 + blane;

            int idx;
            if (lane < 5) {
                idx = lane;
            } else if (lane < 10) {
                int s = lane - 5;
                idx = (s < 4) ? (8 + 2 * s) : 5;
            } else if (lane < 15) {
                int s = lane - 10;
                idx = (s < 4) ? (9 + 2 * s) : 6;
            } else {
                ag[(size_t)n * 8 + (lane - 15)] = vA;
                if (hb) ag[(size_t)(n + 1) * 8 + (lane - 15)] = vB;
                idx = -1;
            }
            if (idx >= 0) {
                kq[(size_t)n * 16 + idx] = vA;
                if (hb) kq[(size_t)(n + 1) * 16 + idx] = vB;
            }
        }
        __syncwarp();
        n = nn;
    }
}

// ---------------------------------------------------------------------------
// K1b: edge-attr GEMV, full occupancy (pure eatt stream).
__global__ __launch_bounds__(256) void edge_gemv(
    const float* __restrict__ eatt,
    const float* __restrict__ We1, const float* __restrict__ be1,
    const float* __restrict__ We2, const float* __restrict__ be2,
    int E)
{
    int tid = threadIdx.x;
    int c   = tid & 3;
    int grp = (tid >> 2) & 7;
    int wid = tid >> 5;

    unsigned long long w01[8], w23[8], w4e[8];
#pragma unroll
    for (int i = 0; i < 8; i++) {
        int col = c * 8 + i;
        w01[i] = pack2(__ldg(&We1[col * 5 + 0]), __ldg(&We1[col * 5 + 1]));
        w23[i] = pack2(__ldg(&We1[col * 5 + 2]), __ldg(&We1[col * 5 + 3]));
        w4e[i] = pack2(__ldg(&We1[col * 5 + 4]), __ldg(&We2[col]));
    }
    float b0 = __ldg(&be1[0]), b1 = __ldg(&be1[1]), b2 = __ldg(&be1[2]);
    float b3 = __ldg(&be1[3]), b4 = __ldg(&be1[4]);
    float bec2 = __ldg(be2);

    const float4* ea4 = (const float4*)eatt;
    const int WTOT  = gridDim.x * 8;
    const int estep = 2 * WTOT * 8;
    int wg = blockIdx.x * 8 + wid;

    int ew = wg * 8;
    float4 a0, a1, q0, q1;
    if (ew < E) {
        int eA = ew + grp;
        int eB = ew + WTOT * 8 + grp;
        size_t iA = (size_t)(eA < E ? eA : 0);
        size_t iB = (size_t)(eB < E ? eB : 0);
        a0 = __ldg(&ea4[iA * 8 + c * 2]);
        a1 = __ldg(&ea4[iA * 8 + c * 2 + 1]);
        q0 = __ldg(&ea4[iB * 8 + c * 2]);
        q1 = __ldg(&ea4[iB * 8 + c * 2 + 1]);
    }

    while (ew < E) {
        int ewn = ew + estep;
        float4 na0, na1, nq0, nq1;
        if (ewn < E) {
            int eA = ewn + grp;
            int eB = ewn + WTOT * 8 + grp;
            size_t iA = (size_t)(eA < E ? eA : 0);
            size_t iB = (size_t)(eB < E ? eB : 0);
            na0 = __ldg(&ea4[iA * 8 + c * 2]);
            na1 = __ldg(&ea4[iA * 8 + c * 2 + 1]);
            nq0 = __ldg(&ea4[iB * 8 + c * 2]);
            nq1 = __ldg(&ea4[iB * 8 + c * 2 + 1]);
        }

        int eA = ew + grp;
        int eB = ew + WTOT * 8 + grp;
        bool vA = eA < E, vB = eB < E;

        unsigned long long pA01 = 0ull, pA23 = 0ull, pA4e = 0ull;
        unsigned long long pB01 = 0ull, pB23 = 0ull, pB4e = 0ull;
        float xsA[8] = {a0.x, a0.y, a0.z, a0.w, a1.x, a1.y, a1.z, a1.w};
        float xsB[8] = {q0.x, q0.y, q0.z, q0.w, q1.x, q1.y, q1.z, q1.w};
#pragma unroll
        for (int i = 0; i < 8; i++) {
            unsigned long long xa = pack2(xsA[i], xsA[i]);
            unsigned long long xb = pack2(xsB[i], xsB[i]);
            fma2(pA01, xa, w01[i]); fma2(pA23, xa, w23[i]); fma2(pA4e, xa, w4e[i]);
            fma2(pB01, xb, w01[i]); fma2(pB23, xb, w23[i]); fma2(pB4e, xb, w4e[i]);
        }
#pragma unroll
        for (int off = 2; off > 0; off >>= 1) {
            pA01 = add2(pA01, __shfl_xor_sync(0xffffffffu, pA01, off, 4));
            pA23 = add2(pA23, __shfl_xor_sync(0xffffffffu, pA23, off, 4));
            pA4e = add2(pA4e, __shfl_xor_sync(0xffffffffu, pA4e, off, 4));
            pB01 = add2(pB01, __shfl_xor_sync(0xffffffffu, pB01, off, 4));
            pB23 = add2(pB23, __shfl_xor_sync(0xffffffffu, pB23, off, 4));
            pB4e = add2(pB4e, __shfl_xor_sync(0xffffffffu, pB4e, off, 4));
        }
        float eA0, eA1, eA2, eA3, eA4, eAc2;
        unpack2(pA01, eA0, eA1); unpack2(pA23, eA2, eA3); unpack2(pA4e, eA4, eAc2);
        float eB0, eB1, eB2, eB3, eB4, eBc2;
        unpack2(pB01, eB0, eB1); unpack2(pB23, eB2, eB3); unpack2(pB4e, eB4, eBc2);

        if (vA) {
            if (c == 0)      g_e1a[eA] = make_float4(eA0 + b0, eA1 + b1, eA2 + b2, eA3 + b3);
            else if (c == 1) g_e1b[eA] = eA4 + b4;
            else if (c == 2) g_e2[eA]  = eAc2 + bec2;
        }
        if (vB) {
            if (c == 0)      g_e1a[eB] = make_float4(eB0 + b0, eB1 + b1, eB2 + b2, eB3 + b3);
            else if (c == 1) g_e1b[eB] = eB4 + b4;
            else if (c == 2) g_e2[eB]  = eBc2 + bec2;
        }

        a0 = na0; a1 = na1; q0 = nq0; q1 = nq1;
        ew = ewn;
    }
}

// ---------------------------------------------------------------------------
// K2: conv1 gate + aggregate. One thread per edge, 2 edges/thread, full grid.
__global__ __launch_bounds__(256) void gate_agg(const int* __restrict__ ei, int E)
{
    int half = ((E + 511) / 512) * 256;
    int gid  = blockIdx.x * 256 + threadIdx.x;
    if (gid >= half) return;

    float* agf = (float*)g_aggv;

    int eA = gid;
    int eB = gid + half;
    bool vB = eB < E;
    size_t iB = (size_t)(vB ? eB : 0);

    int sA = __ldg(&ei[eA]), dA = __ldg(&ei[E + eA]);
    int sB = __ldg(&ei[iB]), dB = __ldg(&ei[E + iB]);

    float4 eA03 = __ldg(&g_e1a[eA]);
    float  eA4  = __ldg(&g_e1b[eA]);
    float4 eB03 = __ldg(&g_e1a[iB]);
    float  eB4  = __ldg(&g_e1b[iB]);

    float4 kA03 = __ldg(&g_kqv1[(size_t)dA * 4]);
    float4 kA4  = __ldg(&g_kqv1[(size_t)dA * 4 + 1]);
    float4 sA4  = __ldg(&g_kqv1[(size_t)sA * 4 + 1]);
    float4 qA01 = __ldg(&g_kqv1[(size_t)sA * 4 + 2]);
    float4 qA23 = __ldg(&g_kqv1[(size_t)sA * 4 + 3]);

    float4 kB03 = __ldg(&g_kqv1[(size_t)dB * 4]);
    float4 kB4  = __ldg(&g_kqv1[(size_t)dB * 4 + 1]);
    float4 sB4  = __ldg(&g_kqv1[(size_t)sB * 4 + 1]);
    float4 qB01 = __ldg(&g_kqv1[(size_t)sB * 4 + 2]);
    float4 qB23 = __ldg(&g_kqv1[(size_t)sB * 4 + 3]);

    {
        float m0 = fast_sigmoid(kA03.x + qA01.x + 2.f * eA03.x) * (qA01.y + eA03.x);
        float m1 = fast_sigmoid(kA03.y + qA01.z + 2.f * eA03.y) * (qA01.w + eA03.y);
        float m2 = fast_sigmoid(kA03.z + qA23.x + 2.f * eA03.z) * (qA23.y + eA03.z);
        float m3 = fast_sigmoid(kA03.w + qA23.z + 2.f * eA03.w) * (qA23.w + eA03.w);
        float m4 = fast_sigmoid(kA4.x  + sA4.y  + 2.f * eA4)    * (sA4.z  + eA4);
        atomicAdd(&g_aggv[(size_t)dA * 2], make_float4(m0, m1, m2, m3));
        atomicAdd(&agf[(size_t)dA * 8 + 4], m4);
    }
    if (vB) {
        float m0 = fast_sigmoid(kB03.x + qB01.x + 2.f * eB03.x) * (qB01.y + eB03.x);
        float m1 = fast_sigmoid(kB03.y + qB01.z + 2.f * eB03.y) * (qB01.w + eB03.y);
        float m2 = fast_sigmoid(kB03.z + qB23.x + 2.f * eB03.z) * (qB23.y + eB03.z);
        float m3 = fast_sigmoid(kB03.w + qB23.z + 2.f * eB03.w) * (qB23.w + eB03.w);
        float m4 = fast_sigmoid(kB4.x  + sB4.y  + 2.f * eB4)    * (sB4.z  + eB4);
        atomicAdd(&g_aggv[(size_t)dB * 2], make_float4(m0, m1, m2, m3));
        atomicAdd(&agf[(size_t)dB * 8 + 4], m4);
    }
}

// ---------------------------------------------------------------------------
// K3a: GraphNorm statistics — R1-proven form: warp-uniform detection,
// butterfly reduce, DIRECT global atomics from lane 0 (no smem staging).
__global__ __launch_bounds__(256) void gnorm_stats(const int* __restrict__ batch, int N)
{
    int n    = blockIdx.x * 256 + threadIdx.x;
    int lane = threadIdx.x & 31;
    const float* agf = (const float*)g_aggv;

    bool valid = n < N;
    int g  = valid ? __ldg(&batch[n]) : 0;
    int g0 = __shfl_sync(0xffffffffu, g, 0);
    bool uni = __all_sync(0xffffffffu, valid && (g == g0));

    float v[5];
    float4 v4 = valid ? __ldg((const float4*)(agf + (size_t)n * 8))
                      : make_float4(0.f, 0.f, 0.f, 0.f);
    float  v5 = valid ? __ldg(agf + (size_t)n * 8 + 4) : 0.f;
    v[0] = v4.x; v[1] = v4.y; v[2] = v4.z; v[3] = v4.w; v[4] = v5;

    if (uni) {
#pragma unroll
        for (int h = 0; h < 5; h++) {
            float sv = v[h], sq = v[h] * v[h];
#pragma unroll
            for (int off = 16; off > 0; off >>= 1) {
                sv += __shfl_xor_sync(0xffffffffu, sv, off);
                sq += __shfl_xor_sync(0xffffffffu, sq, off);
            }
            if (lane == 0) {
                atomicAdd(&g_gsum[g0 * 5 + h], sv);
                atomicAdd(&g_gsq[g0 * 5 + h], sq);
            }
        }
        if (lane == 0) atomicAdd(&g_gcnt[g0], 32.f);
    } else if (valid) {
#pragma unroll
        for (int h = 0; h < 5; h++) {
            atomicAdd(&g_gsum[g * 5 + h], v[h]);
            atomicAdd(&g_gsq[g * 5 + h], v[h] * v[h]);
        }
        atomicAdd(&g_gcnt[g], 1.f);
    }
}

// ---------------------------------------------------------------------------
// K3b: norm + relu + conv2 node projections. Each block redundantly builds
// the 320-entry (A,B) affine table in smem (reads are L2-hits), then applies.
__global__ __launch_bounds__(256) void node_proj2(
    const int* __restrict__ batch,
    const float* __restrict__ gw, const float* __restrict__ gb,
    const float* __restrict__ gms,
    const float* __restrict__ Wk2, const float* __restrict__ bk2,
    const float* __restrict__ Wq2, const float* __restrict__ bq2,
    const float* __restrict__ Wv2, const float* __restrict__ bv2,
    const float* __restrict__ Ws2, const float* __restrict__ b2,
    float* __restrict__ out, int N)
{
    __shared__ float sA[NGRP * 5], sB[NGRP * 5];
    int tid = threadIdx.x;
    const float* agf = (const float*)g_aggv;

    for (int t = tid; t < NGRP * 5; t += 256) {
        int g = t / 5, h = t % 5;
        float cnt  = fmaxf(g_gcnt[g], 1.f);
        float mean = g_gsum[t] / cnt;
        float ex2  = g_gsq[t]  / cnt;
        float ms   = __ldg(&gms[h]);
        float d    = mean * ms;
        float var  = ex2 - 2.f * d * mean + d * d;
        float inv  = rsqrtf(var + 1e-5f);
        float wv   = __ldg(&gw[h]);
        sA[t] = wv * inv;
        sB[t] = __ldg(&gb[h]) - wv * inv * d;
    }
    __syncthreads();

    int n = blockIdx.x * 256 + tid;
    if (n >= N) return;

    int g = __ldg(&batch[n]);
    float4 a4 = __ldg((const float4*)(agf + (size_t)n * 8));
    float  a5 = __ldg(agf + (size_t)n * 8 + 4);
    float av[5] = {a4.x, a4.y, a4.z, a4.w, a5};
    float k2 = __ldg(bk2), q2 = __ldg(bq2), v2 = __ldg(bv2), s2 = __ldg(b2);
#pragma unroll
    for (int h = 0; h < 5; h++) {
        float hv = fmaxf(fmaf(sA[g * 5 + h], av[h], sB[g * 5 + h]), 0.f);
        k2 = fmaf(hv, __ldg(&Wk2[h]), k2);
        q2 = fmaf(hv, __ldg(&Wq2[h]), q2);
        v2 = fmaf(hv, __ldg(&Wv2[h]), v2);
        s2 = fmaf(hv, __ldg(&Ws2[h]), s2);
    }
    g_kqv2[n] = make_float4(k2, q2, v2, 0.f);
    out[n]    = s2;
}

// ---------------------------------------------------------------------------
// K3c: conv2 edge pass — full-occupancy grid, 2 edges/thread.
__global__ __launch_bounds__(256) void edge_pass2(const int* __restrict__ ei,
                                                  float* __restrict__ out, int E)
{
    int half = ((E + 511) / 512) * 256;
    int gid  = blockIdx.x * 256 + threadIdx.x;
    if (gid >= half) return;

    int eA = gid;
    int eB = gid + half;
    bool vB = eB < E;
    size_t iB = (size_t)(vB ? eB : 0);

    int sa = __ldg(&ei[eA]), da = __ldg(&ei[E + eA]);
    int sb = __ldg(&ei[iB]), db = __ldg(&ei[E + iB]);
    float eva = __ldg(&g_e2[eA]);
    float evb = __ldg(&g_e2[iB]);
    float4 da4 = __ldg(&g_kqv2[da]);
    float4 sa4 = __ldg(&g_kqv2[sa]);
    float4 db4 = __ldg(&g_kqv2[db]);
    float4 sb4 = __ldg(&g_kqv2[sb]);

    float ga = fast_sigmoid(da4.x + sa4.y + 2.f * eva);
    atomicAdd(&out[da], ga * (sa4.z + eva));
    if (vB) {
        float gbv = fast_sigmoid(db4.x + sb4.y + 2.f * evb);
        atomicAdd(&out[db], gbv * (sb4.z + evb));
    }
}

// ---------------------------------------------------------------------------
__global__ void final_sig(float* __restrict__ out, int N)
{
    int i = blockIdx.x * 256 + threadIdx.x;
    int n4 = N >> 2;
    if (i < n4) {
        float4* o4 = (float4*)out;
        float4 v = o4[i];
        v.x = fast_sigmoid(v.x);
        v.y = fast_sigmoid(v.y);
        v.z = fast_sigmoid(v.z);
        v.w = fast_sigmoid(v.w);
        o4[i] = v;
    } else {
        int n = n4 * 4 + (i - n4);
        if (n < N) out[n] = fast_sigmoid(out[n]);
    }
}

// ---------------------------------------------------------------------------
extern "C" void kernel_launch(void* const* d_in, const int* in_sizes, int n_in,
                              void* d_out, int out_size)
{
    const float* x     = (const float*)d_in[0];
    const float* eatt  = (const float*)d_in[1];
    const int*   ei    = (const int*)d_in[2];
    const int*   batch = (const int*)d_in[3];
    const float* Wk1 = (const float*)d_in[4];
    const float* bk1 = (const float*)d_in[5];
    const float* Wq1 = (const float*)d_in[6];
    const float* bq1 = (const float*)d_in[7];
    const float* Wv1 = (const float*)d_in[8];
    const float* bv1 = (const float*)d_in[9];
    const float* We1 = (const float*)d_in[10];
    const float* be1 = (const float*)d_in[11];
    const float* Ws1 = (const float*)d_in[12];
    const float* b1  = (const float*)d_in[13];
    const float* gw  = (const float*)d_in[14];
    const float* gb  = (const float*)d_in[15];
    const float* gms = (const float*)d_in[16];
    const float* Wk2 = (const float*)d_in[17];
    const float* bk2 = (const float*)d_in[18];
    const float* Wq2 = (const float*)d_in[19];
    const float* bq2 = (const float*)d_in[20];
    const float* Wv2 = (const float*)d_in[21];
    const float* bv2 = (const float*)d_in[22];
    const float* We2 = (const float*)d_in[23];
    const float* be2 = (const float*)d_in[24];
    const float* Ws2 = (const float*)d_in[25];
    const float* b2  = (const float*)d_in[26];
    float* out = (float*)d_out;

    int N = in_sizes[3];
    int E = in_sizes[2] / 2;
    if (N > NMAX) N = NMAX;
    if (E > EMAX) E = EMAX;

    int nb  = (N + 255) / 256;
    int gb2 = (E + 511) / 512;
    int sb  = ((N >> 2) + (N & 3 ? (N & 3) : 0) + 255) / 256 + 1;

    node_proj1<<<148, 256>>>(x, Wk1, bk1, Wq1, bq1, Wv1, bv1, Ws1, b1, N);
    edge_gemv<<<1184, 256>>>(eatt, We1, be1, We2, be2, E);
    gate_agg<<<gb2, 256>>>(ei, E);
    gnorm_stats<<<nb, 256>>>(batch, N);
    node_proj2<<<nb, 256>>>(batch, gw, gb, gms,
                            Wk2, bk2, Wq2, bq2, Wv2, bv2, Ws2, b2, out, N);
    edge_pass2<<<gb2, 256>>>(ei, out, E);
    final_sig<<<sb, 256>>>(out, N);
}

// round 17
// speedup vs baseline: 1.3550x; 1.0710x over previous
#include <cuda_runtime.h>

// ---------------- problem constants ----------------------------------------
#define NMAX 100000
#define EMAX 1600000
#define NGRP 64

// ---------------- scratch (__device__ globals) -----------------------------
// per node 16 floats (64B): [k0..k3][k4,q4,v4,_][q0,v0,q1,v1][q2,v2,q3,v3]
__device__ float4   g_kqv1[NMAX * 4];
__device__ float4   g_aggv[NMAX * 2];    // per node 8 f: conv1 agg in [0..5)
__device__ float    g_e2[EMAX];          // per-edge conv2 edge projection (+bias)
__device__ float4   g_kqv2[NMAX];        // conv2 node proj (k2,q2,v2,_)
__device__ float    g_gsum[NGRP * 5];
__device__ float    g_gsq[NGRP * 5];
__device__ float    g_gcnt[NGRP];

// sigmoid via MUFU.TANH: 1 MUFU instead of 2. rel_err ~1e-6, well under 1e-3.
__device__ __forceinline__ float fast_sigmoid(float z) {
    float t;
    asm("tanh.approx.f32 %0, %1;" : "=f"(t) : "f"(z * 0.5f));
    return fmaf(t, 0.5f, 0.5f);
}

// ---- packed f32x2 helpers (ptxas won't emit FFMA2/FADD2 from C++) ---------
__device__ __forceinline__ unsigned long long pack2(float a, float b) {
    unsigned long long r;
    asm("mov.b64 %0, {%1, %2};" : "=l"(r) : "f"(a), "f"(b));
    return r;
}
__device__ __forceinline__ void unpack2(unsigned long long v, float& a, float& b) {
    asm("mov.b64 {%0, %1}, %2;" : "=f"(a), "=f"(b) : "l"(v));
}
__device__ __forceinline__ void fma2(unsigned long long& d,
                                     unsigned long long a, unsigned long long b) {
    asm("fma.rn.f32x2 %0, %1, %2, %0;" : "+l"(d) : "l"(a), "l"(b));
}
__device__ __forceinline__ unsigned long long add2(unsigned long long a,
                                                   unsigned long long b) {
    unsigned long long r;
    asm("add.rn.f32x2 %0, %1, %2;" : "=l"(r) : "l"(a), "l"(b));
    return r;
}

// ---------------------------------------------------------------------------
// K1: conv1 node GEMM (R5 champion: 1 block/SM, warp-per-node, 80 u64 weight
// regs, two nodes/iter for ILP, smem transpose reduce).
__global__ __launch_bounds__(256, 1) void node_proj1(
    const float* __restrict__ x,
    const float* __restrict__ Wk, const float* __restrict__ bk,
    const float* __restrict__ Wq, const float* __restrict__ bq,
    const float* __restrict__ Wv, const float* __restrict__ bv,
    const float* __restrict__ Ws, const float* __restrict__ bs,
    int N)
{
    __shared__ __align__(16) float sbuf[10240];   // 40KB, dual-purpose

    int tid  = threadIdx.x;
    int lane = tid & 31;
    int wid  = tid >> 5;

    if (blockIdx.x == 0) {                        // fold zero_stats
        for (int i = tid; i < NGRP * 5; i += 256) { g_gsum[i] = 0.f; g_gsq[i] = 0.f; }
        if (tid < NGRP) g_gcnt[tid] = 0.f;
    }

    for (int i = tid; i < 256 * 20; i += 256) {
        int c = i / 20, h = i % 20;
        float v;
        if (h < 5)       v = Wk[c * 5 + h];
        else if (h < 10) v = Wq[c * 5 + h - 5];
        else if (h < 15) v = Wv[c * 5 + h - 10];
        else             v = Ws[c * 5 + h - 15];
        sbuf[c * 21 + h] = v;
    }
    __syncthreads();

    unsigned long long w2[80];
#pragma unroll
    for (int i = 0; i < 8; i++) {
        int c = lane * 8 + i;
#pragma unroll
        for (int p = 0; p < 10; p++)
            w2[i * 10 + p] = pack2(sbuf[c * 21 + 2 * p], sbuf[c * 21 + 2 * p + 1]);
    }
    __syncthreads();

    float blane = 0.f;
    if (lane < 5)       blane = __ldg(&bk[lane]);
    else if (lane < 10) blane = __ldg(&bq[lane - 5]);
    else if (lane < 15) blane = __ldg(&bv[lane - 10]);
    else if (lane < 20) blane = __ldg(&bs[lane - 15]);

    float* redA = &sbuf[wid * 1280];
    float* redB = redA + 640;
    float* kq   = (float*)g_kqv1;
    float* ag   = (float*)g_aggv;

    int warp = blockIdx.x * 8 + wid;
    int step = gridDim.x * 8 * 2;

    int n = warp * 2;
    float4 a0A, a1A, a0B, a1B;
    if (n < N) {
        const float4* xr = (const float4*)(x + (size_t)n * 256 + lane * 8);
        a0A = __ldg(xr); a1A = __ldg(xr + 1);
    }
    if (n + 1 < N) {
        const float4* xr = (const float4*)(x + (size_t)(n + 1) * 256 + lane * 8);
        a0B = __ldg(xr); a1B = __ldg(xr + 1);
    }

    while (n < N) {
        float4 cA0 = a0A, cA1 = a1A, cB0 = a0B, cB1 = a1B;
        bool hb = (n + 1) < N;
        int nn = n + step;
        if (nn < N) {
            const float4* xr = (const float4*)(x + (size_t)nn * 256 + lane * 8);
            a0A = __ldg(xr); a1A = __ldg(xr + 1);
        }
        if (nn + 1 < N) {
            const float4* xr = (const float4*)(x + (size_t)(nn + 1) * 256 + lane * 8);
            a0B = __ldg(xr); a1B = __ldg(xr + 1);
        }

        unsigned long long accA[10], accB[10];
#pragma unroll
        for (int p = 0; p < 10; p++) { accA[p] = 0ull; accB[p] = 0ull; }

        float xA[8] = {cA0.x, cA0.y, cA0.z, cA0.w, cA1.x, cA1.y, cA1.z, cA1.w};
        float xB[8] = {cB0.x, cB0.y, cB0.z, cB0.w, cB1.x, cB1.y, cB1.z, cB1.w};
#pragma unroll
        for (int i = 0; i < 8; i++) {
            unsigned long long xa = pack2(xA[i], xA[i]);
            unsigned long long xb = pack2(xB[i], xB[i]);
#pragma unroll
            for (int p = 0; p < 10; p++) {
                fma2(accA[p], xa, w2[i * 10 + p]);
                fma2(accB[p], xb, w2[i * 10 + p]);
            }
        }

        {
            ulonglong2* dA = (ulonglong2*)(redA + lane * 20);
            ulonglong2* dB = (ulonglong2*)(redB + lane * 20);
#pragma unroll
            for (int q = 0; q < 5; q++) {
                dA[q] = make_ulonglong2(accA[2 * q], accA[2 * q + 1]);
                dB[q] = make_ulonglong2(accB[2 * q], accB[2 * q + 1]);
            }
        }
        __syncwarp();

        if (lane < 20) {
            float sA0 = 0.f, sA1 = 0.f, sB0 = 0.f, sB1 = 0.f;
#pragma unroll
            for (int l = 0; l < 32; l += 2) {
                sA0 += redA[(l + 0) * 20 + lane];
                sA1 += redA[(l + 1) * 20 + lane];
                sB0 += redB[(l + 0) * 20 + lane];
                sB1 += redB[(l + 1) * 20 + lane];
            }
            float vA = sA0 + sA1 + blane;
            float vB = sB0 + sB1 + blane;

            int idx;
            if (lane < 5) {
                idx = lane;
            } else if (lane < 10) {
                int s = lane - 5;
                idx = (s < 4) ? (8 + 2 * s) : 5;
            } else if (lane < 15) {
                int s = lane - 10;
                idx = (s < 4) ? (9 + 2 * s) : 6;
            } else {
                ag[(size_t)n * 8 + (lane - 15)] = vA;
                if (hb) ag[(size_t)(n + 1) * 8 + (lane - 15)] = vB;
                idx = -1;
            }
            if (idx >= 0) {
                kq[(size_t)n * 16 + idx] = vA;
                if (hb) kq[(size_t)(n + 1) * 16 + idx] = vB;
            }
        }
        __syncwarp();
        n = nn;
    }
}

// ---------------------------------------------------------------------------
// K2: FUSED conv1 edge pass: eatt GEMV + gate + aggregate (+ e2 store).
// 4 lanes/edge, 2 edges/iter. The e1 intermediate never touches DRAM
// (64 MB round trip saved). Lane c owns feature c; lane 3 rides feature 4;
// lane 2 stores e2; lane 0 issues the float4 message atomic.
__global__ __launch_bounds__(256) void edge_conv1(
    const float* __restrict__ eatt, const int* __restrict__ ei,
    const float* __restrict__ We1, const float* __restrict__ be1,
    const float* __restrict__ We2, const float* __restrict__ be2,
    int E)
{
    int tid = threadIdx.x;
    int c   = tid & 3;
    int grp = (tid >> 2) & 7;
    int wid = tid >> 5;

    unsigned long long w01[8], w23[8], w4e[8];
#pragma unroll
    for (int i = 0; i < 8; i++) {
        int col = c * 8 + i;
        w01[i] = pack2(__ldg(&We1[col * 5 + 0]), __ldg(&We1[col * 5 + 1]));
        w23[i] = pack2(__ldg(&We1[col * 5 + 2]), __ldg(&We1[col * 5 + 3]));
        w4e[i] = pack2(__ldg(&We1[col * 5 + 4]), __ldg(&We2[col]));
    }
    float behc = __ldg(&be1[c]);        // bias for this lane's feature
    float beh4 = __ldg(&be1[4]);
    float bec2 = __ldg(be2);

    const float*  kqf = (const float*)g_kqv1;
    const float4* ea4 = (const float4*)eatt;
    float*        agf = (float*)g_aggv;

    const int WTOT  = gridDim.x * 8;
    const int estep = 2 * WTOT * 8;
    int wg = blockIdx.x * 8 + wid;

    for (int ew = wg * 8; ew < E; ew += estep) {
        int eA = ew + grp;
        int eB = ew + WTOT * 8 + grp;
        bool vA = eA < E, vB = eB < E;
        size_t iA = (size_t)(vA ? eA : 0);
        size_t iB = (size_t)(vB ? eB : 0);

        // ---- index + eatt loads for both edges (issued up front) ----------
        int sA = __ldg(&ei[iA]), dA = __ldg(&ei[E + iA]);
        int sB = __ldg(&ei[iB]), dB = __ldg(&ei[E + iB]);

        float4 a0 = __ldg(&ea4[iA * 8 + c * 2]);
        float4 a1 = __ldg(&ea4[iA * 8 + c * 2 + 1]);
        float4 q0 = __ldg(&ea4[iB * 8 + c * 2]);
        float4 q1 = __ldg(&ea4[iB * 8 + c * 2 + 1]);

        // ---- gathers (dependent on ei; latency hidden under GEMV) ---------
        float  kA  = __ldg(&kqf[(size_t)dA * 16 + c]);
        float2 qvA = __ldg((const float2*)(kqf + (size_t)sA * 16 + 8 + 2 * c));
        float  kB  = __ldg(&kqf[(size_t)dB * 16 + c]);
        float2 qvB = __ldg((const float2*)(kqf + (size_t)sB * 16 + 8 + 2 * c));

        float k4A = 0.f, k4B = 0.f;
        float4 s4A = make_float4(0.f, 0.f, 0.f, 0.f);
        float4 s4B = make_float4(0.f, 0.f, 0.f, 0.f);
        if (c == 3) {
            k4A = __ldg(&kqf[(size_t)dA * 16 + 4]);
            s4A = __ldg((const float4*)(kqf + (size_t)sA * 16 + 4)); // (k4,q4,v4,_)
            k4B = __ldg(&kqf[(size_t)dB * 16 + 4]);
            s4B = __ldg((const float4*)(kqf + (size_t)sB * 16 + 4));
        }

        // ---- GEMV for both edges -------------------------------------------
        unsigned long long pA01 = 0ull, pA23 = 0ull, pA4e = 0ull;
        unsigned long long pB01 = 0ull, pB23 = 0ull, pB4e = 0ull;
        float xsA[8] = {a0.x, a0.y, a0.z, a0.w, a1.x, a1.y, a1.z, a1.w};
        float xsB[8] = {q0.x, q0.y, q0.z, q0.w, q1.x, q1.y, q1.z, q1.w};
#pragma unroll
        for (int i = 0; i < 8; i++) {
            unsigned long long xa = pack2(xsA[i], xsA[i]);
            unsigned long long xb = pack2(xsB[i], xsB[i]);
            fma2(pA01, xa, w01[i]); fma2(pA23, xa, w23[i]); fma2(pA4e, xa, w4e[i]);
            fma2(pB01, xb, w01[i]); fma2(pB23, xb, w23[i]); fma2(pB4e, xb, w4e[i]);
        }
#pragma unroll
        for (int off = 2; off > 0; off >>= 1) {
            pA01 = add2(pA01, __shfl_xor_sync(0xffffffffu, pA01, off, 4));
            pA23 = add2(pA23, __shfl_xor_sync(0xffffffffu, pA23, off, 4));
            pA4e = add2(pA4e, __shfl_xor_sync(0xffffffffu, pA4e, off, 4));
            pB01 = add2(pB01, __shfl_xor_sync(0xffffffffu, pB01, off, 4));
            pB23 = add2(pB23, __shfl_xor_sync(0xffffffffu, pB23, off, 4));
            pB4e = add2(pB4e, __shfl_xor_sync(0xffffffffu, pB4e, off, 4));
        }
        float eA0, eA1, eA2, eA3, eA4, eAc2;
        unpack2(pA01, eA0, eA1); unpack2(pA23, eA2, eA3); unpack2(pA4e, eA4, eAc2);
        float eB0, eB1, eB2, eB3, eB4, eBc2;
        unpack2(pB01, eB0, eB1); unpack2(pB23, eB2, eB3); unpack2(pB4e, eB4, eBc2);

        if (c == 2) {                              // conv2 edge projection
            if (vA) g_e2[eA] = eAc2 + bec2;
            if (vB) g_e2[eB] = eBc2 + bec2;
        }

        // ---- gate + aggregate, edge A ---------------------------------------
        {
            float eh = ((c == 0) ? eA0 : (c == 1) ? eA1 : (c == 2) ? eA2 : eA3) + behc;
            float gate = fast_sigmoid(kA + qvA.x + 2.f * eh);
            float msg  = gate * (qvA.y + eh);
            float m1 = __shfl_sync(0xffffffffu, msg, 1, 4);
            float m2 = __shfl_sync(0xffffffffu, msg, 2, 4);
            float m3 = __shfl_sync(0xffffffffu, msg, 3, 4);
            if (vA) {
                if (c == 0)
                    atomicAdd(&g_aggv[(size_t)dA * 2], make_float4(msg, m1, m2, m3));
                else if (c == 3) {
                    float eh4 = eA4 + beh4;
                    float g4  = fast_sigmoid(k4A + s4A.y + 2.f * eh4);
                    atomicAdd(&agf[(size_t)dA * 8 + 4], g4 * (s4A.z + eh4));
                }
            }
        }
        // ---- gate + aggregate, edge B ---------------------------------------
        {
            float eh = ((c == 0) ? eB0 : (c == 1) ? eB1 : (c == 2) ? eB2 : eB3) + behc;
            float gate = fast_sigmoid(kB + qvB.x + 2.f * eh);
            float msg  = gate * (qvB.y + eh);
            float m1 = __shfl_sync(0xffffffffu, msg, 1, 4);
            float m2 = __shfl_sync(0xffffffffu, msg, 2, 4);
            float m3 = __shfl_sync(0xffffffffu, msg, 3, 4);
            if (vB) {
                if (c == 0)
                    atomicAdd(&g_aggv[(size_t)dB * 2], make_float4(msg, m1, m2, m3));
                else if (c == 3) {
                    float eh4 = eB4 + beh4;
                    float g4  = fast_sigmoid(k4B + s4B.y + 2.f * eh4);
                    atomicAdd(&agf[(size_t)dB * 8 + 4], g4 * (s4B.z + eh4));
                }
            }
        }
    }
}

// ---------------------------------------------------------------------------
// K3a: GraphNorm statistics — warp-uniform detect, butterfly, direct atomics.
__global__ __launch_bounds__(256) void gnorm_stats(const int* __restrict__ batch, int N)
{
    int n    = blockIdx.x * 256 + threadIdx.x;
    int lane = threadIdx.x & 31;
    const float* agf = (const float*)g_aggv;

    bool valid = n < N;
    int g  = valid ? __ldg(&batch[n]) : 0;
    int g0 = __shfl_sync(0xffffffffu, g, 0);
    bool uni = __all_sync(0xffffffffu, valid && (g == g0));

    float v[5];
    float4 v4 = valid ? __ldg((const float4*)(agf + (size_t)n * 8))
                      : make_float4(0.f, 0.f, 0.f, 0.f);
    float  v5 = valid ? __ldg(agf + (size_t)n * 8 + 4) : 0.f;
    v[0] = v4.x; v[1] = v4.y; v[2] = v4.z; v[3] = v4.w; v[4] = v5;

    if (uni) {
#pragma unroll
        for (int h = 0; h < 5; h++) {
            float sv = v[h], sq = v[h] * v[h];
#pragma unroll
            for (int off = 16; off > 0; off >>= 1) {
                sv += __shfl_xor_sync(0xffffffffu, sv, off);
                sq += __shfl_xor_sync(0xffffffffu, sq, off);
            }
            if (lane == 0) {
                atomicAdd(&g_gsum[g0 * 5 + h], sv);
                atomicAdd(&g_gsq[g0 * 5 + h], sq);
            }
        }
        if (lane == 0) atomicAdd(&g_gcnt[g0], 32.f);
    } else if (valid) {
#pragma unroll
        for (int h = 0; h < 5; h++) {
            atomicAdd(&g_gsum[g * 5 + h], v[h]);
            atomicAdd(&g_gsq[g * 5 + h], v[h] * v[h]);
        }
        atomicAdd(&g_gcnt[g], 1.f);
    }
}

// ---------------------------------------------------------------------------
// K3b: norm + relu + conv2 node projections.
__global__ __launch_bounds__(256) void node_proj2(
    const int* __restrict__ batch,
    const float* __restrict__ gw, const float* __restrict__ gb,
    const float* __restrict__ gms,
    const float* __restrict__ Wk2, const float* __restrict__ bk2,
    const float* __restrict__ Wq2, const float* __restrict__ bq2,
    const float* __restrict__ Wv2, const float* __restrict__ bv2,
    const float* __restrict__ Ws2, const float* __restrict__ b2,
    float* __restrict__ out, int N)
{
    __shared__ float sA[NGRP * 5], sB[NGRP * 5];
    int tid = threadIdx.x;
    const float* agf = (const float*)g_aggv;

    for (int t = tid; t < NGRP * 5; t += 256) {
        int g = t / 5, h = t % 5;
        float cnt  = fmaxf(g_gcnt[g], 1.f);
        float mean = g_gsum[t] / cnt;
        float ex2  = g_gsq[t]  / cnt;
        float ms   = __ldg(&gms[h]);
        float d    = mean * ms;
        float var  = ex2 - 2.f * d * mean + d * d;
        float inv  = rsqrtf(var + 1e-5f);
        float wv   = __ldg(&gw[h]);
        sA[t] = wv * inv;
        sB[t] = __ldg(&gb[h]) - wv * inv * d;
    }
    __syncthreads();

    int n = blockIdx.x * 256 + tid;
    if (n >= N) return;

    int g = __ldg(&batch[n]);
    float4 a4 = __ldg((const float4*)(agf + (size_t)n * 8));
    float  a5 = __ldg(agf + (size_t)n * 8 + 4);
    float av[5] = {a4.x, a4.y, a4.z, a4.w, a5};
    float k2 = __ldg(bk2), q2 = __ldg(bq2), v2 = __ldg(bv2), s2 = __ldg(b2);
#pragma unroll
    for (int h = 0; h < 5; h++) {
        float hv = fmaxf(fmaf(sA[g * 5 + h], av[h], sB[g * 5 + h]), 0.f);
        k2 = fmaf(hv, __ldg(&Wk2[h]), k2);
        q2 = fmaf(hv, __ldg(&Wq2[h]), q2);
        v2 = fmaf(hv, __ldg(&Wv2[h]), v2);
        s2 = fmaf(hv, __ldg(&Ws2[h]), s2);
    }
    g_kqv2[n] = make_float4(k2, q2, v2, 0.f);
    out[n]    = s2;
}

// ---------------------------------------------------------------------------
// K3c: conv2 edge pass — full-occupancy grid, 2 edges/thread.
__global__ __launch_bounds__(256) void edge_pass2(const int* __restrict__ ei,
                                                  float* __restrict__ out, int E)
{
    int half = ((E + 511) / 512) * 256;
    int gid  = blockIdx.x * 256 + threadIdx.x;
    if (gid >= half) return;

    int eA = gid;
    int eB = gid + half;
    bool vB = eB < E;
    size_t iB = (size_t)(vB ? eB : 0);

    int sa = __ldg(&ei[eA]), da = __ldg(&ei[E + eA]);
    int sb = __ldg(&ei[iB]), db = __ldg(&ei[E + iB]);
    float eva = __ldg(&g_e2[eA]);
    float evb = __ldg(&g_e2[iB]);
    float4 da4 = __ldg(&g_kqv2[da]);
    float4 sa4 = __ldg(&g_kqv2[sa]);
    float4 db4 = __ldg(&g_kqv2[db]);
    float4 sb4 = __ldg(&g_kqv2[sb]);

    float ga = fast_sigmoid(da4.x + sa4.y + 2.f * eva);
    atomicAdd(&out[da], ga * (sa4.z + eva));
    if (vB) {
        float gbv = fast_sigmoid(db4.x + sb4.y + 2.f * evb);
        atomicAdd(&out[db], gbv * (sb4.z + evb));
    }
}

// ---------------------------------------------------------------------------
__global__ void final_sig(float* __restrict__ out, int N)
{
    int i = blockIdx.x * 256 + threadIdx.x;
    int n4 = N >> 2;
    if (i < n4) {
        float4* o4 = (float4*)out;
        float4 v = o4[i];
        v.x = fast_sigmoid(v.x);
        v.y = fast_sigmoid(v.y);
        v.z = fast_sigmoid(v.z);
        v.w = fast_sigmoid(v.w);
        o4[i] = v;
    } else {
        int n = n4 * 4 + (i - n4);
        if (n < N) out[n] = fast_sigmoid(out[n]);
    }
}

// ---------------------------------------------------------------------------
extern "C" void kernel_launch(void* const* d_in, const int* in_sizes, int n_in,
                              void* d_out, int out_size)
{
    const float* x     = (const float*)d_in[0];
    const float* eatt  = (const float*)d_in[1];
    const int*   ei    = (const int*)d_in[2];
    const int*   batch = (const int*)d_in[3];
    const float* Wk1 = (const float*)d_in[4];
    const float* bk1 = (const float*)d_in[5];
    const float* Wq1 = (const float*)d_in[6];
    const float* bq1 = (const float*)d_in[7];
    const float* Wv1 = (const float*)d_in[8];
    const float* bv1 = (const float*)d_in[9];
    const float* We1 = (const float*)d_in[10];
    const float* be1 = (const float*)d_in[11];
    const float* Ws1 = (const float*)d_in[12];
    const float* b1  = (const float*)d_in[13];
    const float* gw  = (const float*)d_in[14];
    const float* gb  = (const float*)d_in[15];
    const float* gms = (const float*)d_in[16];
    const float* Wk2 = (const float*)d_in[17];
    const float* bk2 = (const float*)d_in[18];
    const float* Wq2 = (const float*)d_in[19];
    const float* bq2 = (const float*)d_in[20];
    const float* Wv2 = (const float*)d_in[21];
    const float* bv2 = (const float*)d_in[22];
    const float* We2 = (const float*)d_in[23];
    const float* be2 = (const float*)d_in[24];
    const float* Ws2 = (const float*)d_in[25];
    const float* b2  = (const float*)d_in[26];
    float* out = (float*)d_out;

    int N = in_sizes[3];
    int E = in_sizes[2] / 2;
    if (N > NMAX) N = NMAX;
    if (E > EMAX) E = EMAX;

    int nb  = (N + 255) / 256;
    int gb2 = (E + 511) / 512;
    int sb  = ((N >> 2) + (N & 3 ? (N & 3) : 0) + 255) / 256 + 1;

    node_proj1<<<148, 256>>>(x, Wk1, bk1, Wq1, bq1, Wv1, bv1, Ws1, b1, N);
    edge_conv1<<<1184, 256>>>(eatt, ei, We1, be1, We2, be2, E);
    gnorm_stats<<<nb, 256>>>(batch, N);
    node_proj2<<<nb, 256>>>(batch, gw, gb, gms,
                            Wk2, bk2, Wq2, bq2, Wv2, bv2, Ws2, b2, out, N);
    edge_pass2<<<gb2, 256>>>(ei, out, E);
    final_sig<<<sb, 256>>>(out, N);
}